// round 1
// baseline (speedup 1.0000x reference)
#include <cuda_runtime.h>
#include <math.h>

// Problem constants
#define BB   16
#define HH   56
#define WW   56
#define CC   192
#define NWIN 1024       // 16 * 8 * 8 windows
#define NTOK 49         // 7*7 tokens per window
#define NHD  6
#define HD   32
#define TTOK 50176      // BB*HH*WW
#define HID  768

// -------- scratch (device globals; no allocation allowed) --------
__device__ float g_qkv[(size_t)NWIN * NTOK * 576];   // [w][n][576]  (q scaled)
__device__ float g_attn[(size_t)NWIN * NTOK * CC];   // [w][n][head*32+d]
__device__ float g_x2[(size_t)TTOK * CC];            // residual stream after attention
__device__ float g_h2[(size_t)TTOK * CC];            // LN2 output
__device__ float g_hid[(size_t)TTOK * HID];          // MLP hidden

// ============================================================
// K1: LN1 + shift + window partition + QKV GEMM (+ q scale)
// grid (NWIN, 3), block 256.  Each block: 49 rows x 192 cols of qkv.
// ============================================================
__global__ __launch_bounds__(256) void k_ln_qkv(
    const float* __restrict__ x, const float* __restrict__ qkv_w,
    const float* __restrict__ qkv_b,
    const float* __restrict__ g1, const float* __restrict__ b1)
{
    __shared__ float a_sm[49][193];
    __shared__ float w_sm[8][192];

    const int w     = blockIdx.x;
    const int gcol0 = blockIdx.y * 192;
    const int b  = w >> 6;
    const int wy = (w >> 3) & 7;
    const int wx = w & 7;
    const int tid  = threadIdx.x;
    const int lane = tid & 31;
    const int warp = tid >> 5;

    // ---- LN phase: one warp per row ----
    for (int n = warp; n < 49; n += 8) {
        int ty = n / 7, tx = n - 7 * ty;
        int hs = (wy * 7 + ty + 3) % 56;   // shifted source row
        int ws = (wx * 7 + tx + 3) % 56;   // shifted source col
        const float* xr = x + ((size_t)(b * 56 + hs) * 56 + ws) * 192;
        float v[6]; float s = 0.f, s2 = 0.f;
        #pragma unroll
        for (int j = 0; j < 6; j++) {
            v[j] = xr[lane + 32 * j];
            s  += v[j];
            s2 += v[j] * v[j];
        }
        #pragma unroll
        for (int o = 16; o > 0; o >>= 1) {
            s  += __shfl_xor_sync(0xffffffffu, s,  o);
            s2 += __shfl_xor_sync(0xffffffffu, s2, o);
        }
        float mean = s * (1.f / 192.f);
        float var  = s2 * (1.f / 192.f) - mean * mean;
        float inv  = rsqrtf(var + 1e-5f);
        #pragma unroll
        for (int j = 0; j < 6; j++) {
            int k = lane + 32 * j;
            a_sm[n][k] = (v[j] - mean) * inv * g1[k] + b1[k];
        }
    }
    __syncthreads();

    // ---- GEMM phase: thread tile 7 rows x 6 cols ----
    const int ty8  = warp;   // row group 0..7 -> rows ty8 + 8*i
    const int tx32 = lane;   // col group     -> cols tx32 + 32*j
    float acc[7][6];
    #pragma unroll
    for (int i = 0; i < 7; i++)
        #pragma unroll
        for (int j = 0; j < 6; j++) acc[i][j] = 0.f;

    for (int kc = 0; kc < 192; kc += 8) {
        #pragma unroll
        for (int e = 0; e < 6; e++) {
            int idx = tid + 256 * e;            // 0..1535
            int r = idx / 192, c = idx - 192 * r;
            w_sm[r][c] = qkv_w[(size_t)(kc + r) * 576 + gcol0 + c];
        }
        __syncthreads();
        #pragma unroll
        for (int kk = 0; kk < 8; kk++) {
            float av[7], wv[6];
            #pragma unroll
            for (int i = 0; i < 7; i++) av[i] = a_sm[ty8 + 8 * i][kc + kk];
            #pragma unroll
            for (int j = 0; j < 6; j++) wv[j] = w_sm[kk][tx32 + 32 * j];
            #pragma unroll
            for (int i = 0; i < 7; i++)
                #pragma unroll
                for (int j = 0; j < 6; j++) acc[i][j] = fmaf(av[i], wv[j], acc[i][j]);
        }
        __syncthreads();
    }

    const float scale = 0.17677669529663687f;   // 32^-0.5
    #pragma unroll
    for (int i = 0; i < 7; i++) {
        int n = ty8 + 8 * i;
        if (n < 49) {
            #pragma unroll
            for (int j = 0; j < 6; j++) {
                int gc = gcol0 + tx32 + 32 * j;
                float v = acc[i][j] + qkv_b[gc];
                if (gc < 192) v *= scale;        // fold softmax scale into q
                g_qkv[((size_t)w * 49 + n) * 576 + gc] = v;
            }
        }
    }
}

// ============================================================
// K2: windowed attention, 1 block per (window, head), 128 threads
// ============================================================
__global__ __launch_bounds__(128) void k_attn(const float* __restrict__ bias_table)
{
    __shared__ float q_sm[49][33];
    __shared__ float k_sm[49][33];
    __shared__ float v_sm[49][33];
    __shared__ float s_sm[49][50];

    const int w    = blockIdx.x;
    const int head = blockIdx.y;
    const int tid  = threadIdx.x;
    const float* base = g_qkv + (size_t)w * 49 * 576 + head * 32;

    for (int idx = tid; idx < 1568; idx += 128) {
        int n = idx >> 5, d = idx & 31;
        q_sm[n][d] = base[n * 576 + d];
        k_sm[n][d] = base[n * 576 + 192 + d];
        v_sm[n][d] = base[n * 576 + 384 + d];
    }
    __syncthreads();

    // scores + relative-position bias
    for (int idx = tid; idx < 2401; idx += 128) {
        int n = idx / 49, m = idx - 49 * n;
        float a = 0.f;
        #pragma unroll
        for (int d = 0; d < 32; d++) a = fmaf(q_sm[n][d], k_sm[m][d], a);
        int i1 = n / 7, j1 = n - 7 * i1;
        int i2 = m / 7, j2 = m - 7 * i2;
        int bidx = (i1 - i2 + 6) * 13 + (j1 - j2 + 6);
        a += bias_table[bidx * 6 + head];
        s_sm[n][m] = a;
    }
    __syncthreads();

    // softmax: one warp per row
    const int lane = tid & 31, warp = tid >> 5;
    for (int n = warp; n < 49; n += 4) {
        float v0 = (lane < 49)      ? s_sm[n][lane]      : -1e30f;
        float v1 = (lane + 32 < 49) ? s_sm[n][lane + 32] : -1e30f;
        float mx = fmaxf(v0, v1);
        #pragma unroll
        for (int o = 16; o > 0; o >>= 1) mx = fmaxf(mx, __shfl_xor_sync(0xffffffffu, mx, o));
        float e0 = (lane < 49)      ? __expf(v0 - mx) : 0.f;
        float e1 = (lane + 32 < 49) ? __expf(v1 - mx) : 0.f;
        float sm = e0 + e1;
        #pragma unroll
        for (int o = 16; o > 0; o >>= 1) sm += __shfl_xor_sync(0xffffffffu, sm, o);
        float inv = 1.f / sm;
        if (lane < 49)      s_sm[n][lane]      = e0 * inv;
        if (lane + 32 < 49) s_sm[n][lane + 32] = e1 * inv;
    }
    __syncthreads();

    // O = P @ V
    float* outp = g_attn + (size_t)w * 49 * 192 + head * 32;
    for (int idx = tid; idx < 1568; idx += 128) {
        int n = idx >> 5, d = idx & 31;
        float a = 0.f;
        #pragma unroll
        for (int m = 0; m < 49; m++) a = fmaf(s_sm[n][m], v_sm[m][d], a);
        outp[n * 192 + d] = a;
    }
}

// ============================================================
// K3: proj GEMM + window reverse/unshift + residual + LN2
// grid NWIN, block 256
// ============================================================
__global__ __launch_bounds__(256) void k_proj(
    const float* __restrict__ x, const float* __restrict__ proj_w,
    const float* __restrict__ proj_b,
    const float* __restrict__ g2, const float* __restrict__ b2)
{
    __shared__ float a_sm[49][193];
    __shared__ float w_sm[8][192];

    const int w  = blockIdx.x;
    const int b  = w >> 6;
    const int wy = (w >> 3) & 7;
    const int wx = w & 7;
    const int tid  = threadIdx.x;
    const int lane = tid & 31;
    const int warp = tid >> 5;

    const float* ap = g_attn + (size_t)w * 49 * 192;
    for (int idx = tid; idx < 9408; idx += 256)
        a_sm[idx / 192][idx % 192] = ap[idx];
    __syncthreads();

    const int ty8 = warp, tx32 = lane;
    float acc[7][6];
    #pragma unroll
    for (int i = 0; i < 7; i++)
        #pragma unroll
        for (int j = 0; j < 6; j++) acc[i][j] = 0.f;

    for (int kc = 0; kc < 192; kc += 8) {
        #pragma unroll
        for (int e = 0; e < 6; e++) {
            int idx = tid + 256 * e;
            int r = idx / 192, c = idx - 192 * r;
            w_sm[r][c] = proj_w[(size_t)(kc + r) * 192 + c];
        }
        __syncthreads();
        #pragma unroll
        for (int kk = 0; kk < 8; kk++) {
            float av[7], wv[6];
            #pragma unroll
            for (int i = 0; i < 7; i++) av[i] = a_sm[ty8 + 8 * i][kc + kk];
            #pragma unroll
            for (int j = 0; j < 6; j++) wv[j] = w_sm[kk][tx32 + 32 * j];
            #pragma unroll
            for (int i = 0; i < 7; i++)
                #pragma unroll
                for (int j = 0; j < 6; j++) acc[i][j] = fmaf(av[i], wv[j], acc[i][j]);
        }
        __syncthreads();
    }

    // epilogue: +bias, +shortcut (un-shifted position), write x2, stage in a_sm
    #pragma unroll
    for (int i = 0; i < 7; i++) {
        int n = ty8 + 8 * i;
        if (n < 49) {
            int tyy = n / 7, txx = n - 7 * tyy;
            int h  = (wy * 7 + tyy + 3) % 56;
            int wc = (wx * 7 + txx + 3) % 56;
            size_t gi = ((size_t)(b * 56 + h) * 56 + wc) * 192;
            #pragma unroll
            for (int j = 0; j < 6; j++) {
                int c = tx32 + 32 * j;
                float v = acc[i][j] + proj_b[c] + x[gi + c];
                g_x2[gi + c] = v;
                a_sm[n][c] = v;
            }
        }
    }
    __syncthreads();

    // LN2 per row -> g_h2 (same spatial layout as x2)
    for (int n = warp; n < 49; n += 8) {
        int tyy = n / 7, txx = n - 7 * tyy;
        int h  = (wy * 7 + tyy + 3) % 56;
        int wc = (wx * 7 + txx + 3) % 56;
        size_t gi = ((size_t)(b * 56 + h) * 56 + wc) * 192;
        float v[6]; float s = 0.f, s2 = 0.f;
        #pragma unroll
        for (int j = 0; j < 6; j++) {
            v[j] = a_sm[n][lane + 32 * j];
            s  += v[j];
            s2 += v[j] * v[j];
        }
        #pragma unroll
        for (int o = 16; o > 0; o >>= 1) {
            s  += __shfl_xor_sync(0xffffffffu, s,  o);
            s2 += __shfl_xor_sync(0xffffffffu, s2, o);
        }
        float mean = s * (1.f / 192.f);
        float var  = s2 * (1.f / 192.f) - mean * mean;
        float inv  = rsqrtf(var + 1e-5f);
        #pragma unroll
        for (int j = 0; j < 6; j++) {
            int k = lane + 32 * j;
            g_h2[gi + k] = (v[j] - mean) * inv * g2[k] + b2[k];
        }
    }
}

// ============================================================
// K4/K5: tiled GEMM, 64x192 tile, BK=16, 8x6 register tiles.
// EPI 0: g_h2 @ w1 + b -> gelu -> g_hid          (K=192, N=768)
// EPI 1: g_hid @ w2 + b + g_x2 -> out            (K=768, N=192)
// ============================================================
template<int EPI>
__global__ __launch_bounds__(256) void k_mlp(
    const float* __restrict__ wmat, const float* __restrict__ bias,
    float* __restrict__ out)
{
    constexpr int K  = (EPI == 0) ? 192 : 768;
    constexpr int Nc = (EPI == 0) ? 768 : 192;

    __shared__ float a_sm[64][17];
    __shared__ float w_sm[16][192];

    const float* A  = (EPI == 0) ? g_h2 : g_hid;
    float* op       = (EPI == 0) ? g_hid : out;

    const int row0 = blockIdx.x * 64;
    const int col0 = blockIdx.y * 192;
    const int tid  = threadIdx.x;
    const int ty8  = tid >> 5;
    const int tx32 = tid & 31;

    float acc[8][6];
    #pragma unroll
    for (int i = 0; i < 8; i++)
        #pragma unroll
        for (int j = 0; j < 6; j++) acc[i][j] = 0.f;

    for (int kc = 0; kc < K; kc += 16) {
        #pragma unroll
        for (int e = 0; e < 4; e++) {
            int idx = tid + 256 * e;          // 0..1023
            int r = idx >> 4, c = idx & 15;
            a_sm[r][c] = A[(size_t)(row0 + r) * K + kc + c];
        }
        #pragma unroll
        for (int e = 0; e < 12; e++) {
            int idx = tid + 256 * e;          // 0..3071
            int r = idx / 192, c = idx - 192 * r;
            w_sm[r][c] = wmat[(size_t)(kc + r) * Nc + col0 + c];
        }
        __syncthreads();
        #pragma unroll
        for (int kk = 0; kk < 16; kk++) {
            float av[8], wv[6];
            #pragma unroll
            for (int i = 0; i < 8; i++) av[i] = a_sm[ty8 + 8 * i][kk];
            #pragma unroll
            for (int j = 0; j < 6; j++) wv[j] = w_sm[kk][tx32 + 32 * j];
            #pragma unroll
            for (int i = 0; i < 8; i++)
                #pragma unroll
                for (int j = 0; j < 6; j++) acc[i][j] = fmaf(av[i], wv[j], acc[i][j]);
        }
        __syncthreads();
    }

    #pragma unroll
    for (int i = 0; i < 8; i++) {
        size_t r = row0 + ty8 + 8 * i;
        #pragma unroll
        for (int j = 0; j < 6; j++) {
            int gc = col0 + tx32 + 32 * j;
            float v = acc[i][j] + bias[gc];
            if (EPI == 0) {
                v = 0.5f * v * (1.0f + erff(v * 0.70710678118654752f)); // exact gelu
            } else {
                v += g_x2[r * Nc + gc];
            }
            op[r * Nc + gc] = v;
        }
    }
}

// ============================================================
extern "C" void kernel_launch(void* const* d_in, const int* in_sizes, int n_in,
                              void* d_out, int out_size)
{
    (void)in_sizes; (void)n_in; (void)out_size;
    const float* x          = (const float*)d_in[0];
    const float* qkv_w      = (const float*)d_in[1];
    const float* qkv_b      = (const float*)d_in[2];
    const float* proj_w     = (const float*)d_in[3];
    const float* proj_b     = (const float*)d_in[4];
    const float* bias_table = (const float*)d_in[5];
    const float* n1g        = (const float*)d_in[6];
    const float* n1b        = (const float*)d_in[7];
    const float* n2g        = (const float*)d_in[8];
    const float* n2b        = (const float*)d_in[9];
    const float* w1         = (const float*)d_in[10];
    const float* b1         = (const float*)d_in[11];
    const float* w2         = (const float*)d_in[12];
    const float* b2         = (const float*)d_in[13];
    float* out = (float*)d_out;

    k_ln_qkv<<<dim3(NWIN, 3), 256>>>(x, qkv_w, qkv_b, n1g, n1b);
    k_attn<<<dim3(NWIN, NHD), 128>>>(bias_table);
    k_proj<<<NWIN, 256>>>(x, proj_w, proj_b, n2g, n2b);
    k_mlp<0><<<dim3(TTOK / 64, 4), 256>>>(w1, b1, out);
    k_mlp<1><<<dim3(TTOK / 64, 1), 256>>>(w2, b2, out);
}

// round 3
// speedup vs baseline: 2.2079x; 2.2079x over previous
#include <cuda_runtime.h>
#include <math.h>
#include <stdint.h>

// ---------------- problem constants ----------------
#define TTOK 50176            // 16*56*56 tokens
#define CC   192
#define HID  768

// ---------------- scratch ----------------
__device__ float g_ln [(size_t)TTOK * CC];    // LN1(x), SHIFTED token layout
__device__ float g_qkv[(size_t)TTOK * 576];   // qkv, shifted layout, q pre-scaled
__device__ float g_ao [(size_t)TTOK * CC];    // attention out, UNSHIFTED layout
__device__ float g_x2 [(size_t)TTOK * CC];    // residual stream after attn
__device__ float g_h2 [(size_t)TTOK * CC];    // LN2 out
__device__ float g_hid[(size_t)TTOK * HID];   // MLP hidden

// ---------------- ptx helpers ----------------
__device__ __forceinline__ uint32_t to_tf32(float x) {
    uint32_t r; asm("cvt.rna.tf32.f32 %0, %1;" : "=r"(r) : "f"(x)); return r;
}
__device__ __forceinline__ void ldsm_x4(uint32_t* r, uint32_t addr) {
    asm volatile("ldmatrix.sync.aligned.m8n8.x4.shared.b16 {%0,%1,%2,%3}, [%4];"
        : "=r"(r[0]), "=r"(r[1]), "=r"(r[2]), "=r"(r[3]) : "r"(addr));
}
__device__ __forceinline__ void mma_tf32(float* c, const uint32_t* a, const uint32_t* b) {
    asm volatile(
        "mma.sync.aligned.m16n8k8.row.col.f32.tf32.tf32.f32 "
        "{%0,%1,%2,%3}, {%4,%5,%6,%7}, {%8,%9}, {%0,%1,%2,%3};"
        : "+f"(c[0]), "+f"(c[1]), "+f"(c[2]), "+f"(c[3])
        : "r"(a[0]), "r"(a[1]), "r"(a[2]), "r"(a[3]), "r"(b[0]), "r"(b[1]));
}

// ============================================================
// LayerNorm kernel. SHIFT=true: reads x at (+3,+3) rolled coords
// (producing the shifted stream); SHIFT=false: straight rows.
// grid 6272, block 256 (8 warps = 8 rows/block)
// ============================================================
template<bool SHIFT>
__global__ __launch_bounds__(256) void k_ln(
    const float* __restrict__ in, const float* __restrict__ g,
    const float* __restrict__ b, float* __restrict__ o)
{
    const int p    = blockIdx.x * 8 + (threadIdx.x >> 5);
    const int lane = threadIdx.x & 31;
    const float* src;
    if (SHIFT) {
        int bb = p / 3136, rem = p % 3136;
        int i = rem / 56, j = rem % 56;
        int si = i + 3; if (si >= 56) si -= 56;
        int sj = j + 3; if (sj >= 56) sj -= 56;
        src = in + ((size_t)(bb * 56 + si) * 56 + sj) * 192;
    } else {
        src = in + (size_t)p * 192;
    }
    float v[6]; float s = 0.f, s2 = 0.f;
    #pragma unroll
    for (int jj = 0; jj < 6; jj++) {
        v[jj] = src[lane + 32 * jj];
        s  += v[jj];
        s2 += v[jj] * v[jj];
    }
    #pragma unroll
    for (int off = 16; off > 0; off >>= 1) {
        s  += __shfl_xor_sync(0xffffffffu, s,  off);
        s2 += __shfl_xor_sync(0xffffffffu, s2, off);
    }
    float mean = s * (1.f / 192.f);
    float var  = s2 * (1.f / 192.f) - mean * mean;
    float inv  = rsqrtf(var + 1e-5f);
    float* dst = o + (size_t)p * 192;
    #pragma unroll
    for (int jj = 0; jj < 6; jj++) {
        int k = lane + 32 * jj;
        dst[k] = (v[jj] - mean) * inv * g[k] + b[k];
    }
}

// ============================================================
// TF32 tensor-core GEMM: C[M,ND] = A[M,KD] @ W[KD,ND] + epilogue
// BM=128, BN=96, BK=16; 256 threads = 8 warps (4 m x 2 n),
// warp tile 32x48 (2 mfrags x 6 nfrags of m16n8k8).
// EPI 0: +bias, scale cols<192 by 32^-0.5 (qkv)
// EPI 1: +bias, exact gelu                 (mlp1)
// EPI 2: +bias, +res                       (proj / mlp2)
// ============================================================
template<int EPI, int KD, int ND>
__global__ __launch_bounds__(256) void k_gemm(
    const float* __restrict__ A, const float* __restrict__ W,
    const float* __restrict__ bias, const float* __restrict__ res,
    float* __restrict__ out)
{
    __shared__ float a_sm[128][20];   // pad 20 -> conflict-free LDSM
    __shared__ float w_sm[16][104];   // pad 104 -> conflict-free B LDS

    const int tid   = threadIdx.x;
    const int lane  = tid & 31;
    const int wid   = tid >> 5;
    const int warpM = wid >> 1;       // 0..3
    const int warpN = wid & 1;        // 0..1
    const int row0  = blockIdx.x * 128;
    const int col0  = blockIdx.y * 96;

    float c[2][6][4];
    #pragma unroll
    for (int i = 0; i < 2; i++)
        #pragma unroll
        for (int j = 0; j < 6; j++)
            #pragma unroll
            for (int q = 0; q < 4; q++) c[i][j][q] = 0.f;

    const int arow = tid >> 2;          // 0..63
    const int akq  = (tid & 3) * 4;     // 0,4,8,12

    // register prefetch buffers
    float4 pa0, pa1;
    float  pw[6];

    {   // prefetch kc = 0
        pa0 = *(const float4*)&A[(size_t)(row0 + arow)      * KD + akq];
        pa1 = *(const float4*)&A[(size_t)(row0 + arow + 64) * KD + akq];
        #pragma unroll
        for (int e = 0; e < 6; e++) {
            int idx = tid + 256 * e; int r = idx / 96, ccx = idx - 96 * r;
            pw[e] = W[(size_t)r * ND + col0 + ccx];
        }
    }

    const uint32_t a_base = (uint32_t)__cvta_generic_to_shared(&a_sm[0][0]);
    const int l15 = lane & 15;
    const int lhi = lane >> 4;

    for (int kc = 0; kc < KD; kc += 16) {
        __syncthreads();
        // store tiles (round to tf32 here; rna beats hw truncation)
        *(float4*)&a_sm[arow][akq] = make_float4(
            __uint_as_float(to_tf32(pa0.x)), __uint_as_float(to_tf32(pa0.y)),
            __uint_as_float(to_tf32(pa0.z)), __uint_as_float(to_tf32(pa0.w)));
        *(float4*)&a_sm[arow + 64][akq] = make_float4(
            __uint_as_float(to_tf32(pa1.x)), __uint_as_float(to_tf32(pa1.y)),
            __uint_as_float(to_tf32(pa1.z)), __uint_as_float(to_tf32(pa1.w)));
        #pragma unroll
        for (int e = 0; e < 6; e++) {
            int idx = tid + 256 * e; int r = idx / 96, ccx = idx - 96 * r;
            w_sm[r][ccx] = __uint_as_float(to_tf32(pw[e]));
        }
        __syncthreads();

        // prefetch next slab (overlaps with compute below)
        if (kc + 16 < KD) {
            pa0 = *(const float4*)&A[(size_t)(row0 + arow)      * KD + kc + 16 + akq];
            pa1 = *(const float4*)&A[(size_t)(row0 + arow + 64) * KD + kc + 16 + akq];
            #pragma unroll
            for (int e = 0; e < 6; e++) {
                int idx = tid + 256 * e; int r = idx / 96, ccx = idx - 96 * r;
                pw[e] = W[(size_t)(kc + 16 + r) * ND + col0 + ccx];
            }
        }

        #pragma unroll
        for (int ks = 0; ks < 2; ks++) {
            const int k0 = ks * 8;
            uint32_t a[2][4];
            #pragma unroll
            for (int i = 0; i < 2; i++) {
                uint32_t addr = a_base
                    + (uint32_t)(((warpM * 32 + 16 * i + l15) * 20 + k0) * 4 + lhi * 16);
                ldsm_x4(a[i], addr);
            }
            uint32_t b[6][2];
            #pragma unroll
            for (int j = 0; j < 6; j++) {
                int n = warpN * 48 + 8 * j + (lane >> 2);
                b[j][0] = __float_as_uint(w_sm[k0 +     (lane & 3)][n]);
                b[j][1] = __float_as_uint(w_sm[k0 + 4 + (lane & 3)][n]);
            }
            #pragma unroll
            for (int i = 0; i < 2; i++)
                #pragma unroll
                for (int j = 0; j < 6; j++)
                    mma_tf32(c[i][j], a[i], b[j]);
        }
    }

    // ---- epilogue ----
    const float qscale = 0.17677669529663687f;   // 32^-0.5
    #pragma unroll
    for (int i = 0; i < 2; i++) {
        #pragma unroll
        for (int j = 0; j < 6; j++) {
            int gc = col0 + warpN * 48 + 8 * j + (lane & 3) * 2;
            float2 bb = *(const float2*)&bias[gc];
            #pragma unroll
            for (int h = 0; h < 2; h++) {
                int r = row0 + warpM * 32 + 16 * i + (lane >> 2) + 8 * h;
                float v0 = c[i][j][2 * h + 0] + bb.x;
                float v1 = c[i][j][2 * h + 1] + bb.y;
                if (EPI == 0) {
                    if (gc < 192) { v0 *= qscale; v1 *= qscale; }
                } else if (EPI == 1) {
                    v0 = 0.5f * v0 * (1.0f + erff(v0 * 0.70710678118654752f));
                    v1 = 0.5f * v1 * (1.0f + erff(v1 * 0.70710678118654752f));
                } else {
                    float2 rr = *(const float2*)&res[(size_t)r * ND + gc];
                    v0 += rr.x; v1 += rr.y;
                }
                *(float2*)&out[(size_t)r * ND + gc] = make_float2(v0, v1);
            }
        }
    }
}

// ============================================================
// Windowed attention: 1 block per (window, head), 128 threads.
// Reads g_qkv (shifted layout, q pre-scaled), writes g_ao
// (unshifted layout — scatter applies the +3 roll).
// ============================================================
__global__ __launch_bounds__(128) void k_attn(const float* __restrict__ bias_table)
{
    __shared__ float q_sm[49][33];
    __shared__ float k_sm[49][33];
    __shared__ float v_sm[49][33];
    __shared__ float s_sm[49][50];

    const int w    = blockIdx.x;
    const int head = blockIdx.y;
    const int tid  = threadIdx.x;
    const int b    = w >> 6;
    const int wy   = (w >> 3) & 7;
    const int wx   = w & 7;

    for (int idx = tid; idx < 1568; idx += 128) {
        int n = idx >> 5, d = idx & 31;
        int ty = n / 7, tx = n - 7 * ty;
        size_t row = ((size_t)(b * 56 + wy * 7 + ty) * 56 + wx * 7 + tx);
        const float* base = g_qkv + row * 576 + head * 32 + d;
        q_sm[n][d] = base[0];
        k_sm[n][d] = base[192];
        v_sm[n][d] = base[384];
    }
    __syncthreads();

    for (int idx = tid; idx < 2401; idx += 128) {
        int n = idx / 49, m = idx - 49 * n;
        float a = 0.f;
        #pragma unroll
        for (int d = 0; d < 32; d++) a = fmaf(q_sm[n][d], k_sm[m][d], a);
        int i1 = n / 7, j1 = n - 7 * i1;
        int i2 = m / 7, j2 = m - 7 * i2;
        int bidx = (i1 - i2 + 6) * 13 + (j1 - j2 + 6);
        a += bias_table[bidx * 6 + head];
        s_sm[n][m] = a;
    }
    __syncthreads();

    const int lane = tid & 31, warp = tid >> 5;
    for (int n = warp; n < 49; n += 4) {
        float v0 = (lane < 49)      ? s_sm[n][lane]      : -1e30f;
        float v1 = (lane + 32 < 49) ? s_sm[n][lane + 32] : -1e30f;
        float mx = fmaxf(v0, v1);
        #pragma unroll
        for (int o = 16; o > 0; o >>= 1) mx = fmaxf(mx, __shfl_xor_sync(0xffffffffu, mx, o));
        float e0 = (lane < 49)      ? __expf(v0 - mx) : 0.f;
        float e1 = (lane + 32 < 49) ? __expf(v1 - mx) : 0.f;
        float sm = e0 + e1;
        #pragma unroll
        for (int o = 16; o > 0; o >>= 1) sm += __shfl_xor_sync(0xffffffffu, sm, o);
        float inv = 1.f / sm;
        if (lane < 49)      s_sm[n][lane]      = e0 * inv;
        if (lane + 32 < 49) s_sm[n][lane + 32] = e1 * inv;
    }
    __syncthreads();

    for (int idx = tid; idx < 1568; idx += 128) {
        int n = idx >> 5, d = idx & 31;
        float a = 0.f;
        #pragma unroll
        for (int m = 0; m < 49; m++) a = fmaf(s_sm[n][m], v_sm[m][d], a);
        int ty = n / 7, tx = n - 7 * ty;
        int oi = wy * 7 + ty + 3; if (oi >= 56) oi -= 56;
        int oj = wx * 7 + tx + 3; if (oj >= 56) oj -= 56;
        g_ao[((size_t)(b * 56 + oi) * 56 + oj) * 192 + head * 32 + d] = a;
    }
}

// ============================================================
extern "C" void kernel_launch(void* const* d_in, const int* in_sizes, int n_in,
                              void* d_out, int out_size)
{
    (void)in_sizes; (void)n_in; (void)out_size;
    const float* x          = (const float*)d_in[0];
    const float* qkv_w      = (const float*)d_in[1];
    const float* qkv_b      = (const float*)d_in[2];
    const float* proj_w     = (const float*)d_in[3];
    const float* proj_b     = (const float*)d_in[4];
    const float* bias_table = (const float*)d_in[5];
    const float* n1g        = (const float*)d_in[6];
    const float* n1b        = (const float*)d_in[7];
    const float* n2g        = (const float*)d_in[8];
    const float* n2b        = (const float*)d_in[9];
    const float* w1         = (const float*)d_in[10];
    const float* b1         = (const float*)d_in[11];
    const float* w2         = (const float*)d_in[12];
    const float* b2         = (const float*)d_in[13];
    float* out = (float*)d_out;

    float* p_ln  = nullptr; cudaGetSymbolAddress((void**)&p_ln,  g_ln);
    float* p_qkv = nullptr; cudaGetSymbolAddress((void**)&p_qkv, g_qkv);
    float* p_ao  = nullptr; cudaGetSymbolAddress((void**)&p_ao,  g_ao);
    float* p_x2  = nullptr; cudaGetSymbolAddress((void**)&p_x2,  g_x2);
    float* p_h2  = nullptr; cudaGetSymbolAddress((void**)&p_h2,  g_h2);
    float* p_hid = nullptr; cudaGetSymbolAddress((void**)&p_hid, g_hid);

    // LN1 + shift -> shifted token stream
    k_ln<true><<<6272, 256>>>(x, n1g, n1b, p_ln);
    // QKV GEMM (position-wise, shifted layout), q pre-scaled
    k_gemm<0, 192, 576><<<dim3(392, 6), 256>>>(p_ln, qkv_w, qkv_b, nullptr, p_qkv);
    // windowed attention (+rel-pos bias, softmax), scatter to unshifted
    k_attn<<<dim3(1024, 6), 128>>>(bias_table);
    // proj GEMM + residual(x) -> x2
    k_gemm<2, 192, 192><<<dim3(392, 2), 256>>>(p_ao, proj_w, proj_b, x, p_x2);
    // LN2
    k_ln<false><<<6272, 256>>>(p_x2, n2g, n2b, p_h2);
    // MLP
    k_gemm<1, 192, 768><<<dim3(392, 8), 256>>>(p_h2, w1, b1, nullptr, p_hid);
    k_gemm<2, 768, 192><<<dim3(392, 2), 256>>>(p_hid, w2, b2, p_x2, out);
}

// round 5
// speedup vs baseline: 2.4787x; 1.1226x over previous
#include <cuda_runtime.h>
#include <math.h>
#include <stdint.h>

// ---------------- problem constants ----------------
#define TTOK 50176            // 16*56*56 tokens
#define CC   192
#define HID  768

// ---------------- scratch ----------------
__device__ float g_ln [(size_t)TTOK * CC];    // LN1(x), SHIFTED layout (tf32-rounded)
__device__ float g_qkv[(size_t)TTOK * 576];   // qkv, shifted layout, q pre-scaled
__device__ float g_ao [(size_t)TTOK * CC];    // attn out, UNSHIFTED (tf32-rounded)
__device__ float g_x2 [(size_t)TTOK * CC];    // residual stream after attn
__device__ float g_h2 [(size_t)TTOK * CC];    // LN2 out (tf32-rounded)
__device__ float g_hid[(size_t)TTOK * HID];   // MLP hidden (tf32-rounded)
// transposed (tf32-rounded) weights: WT[n][k]
__device__ float g_qkvT[576 * 192];
__device__ float g_projT[192 * 192];
__device__ float g_w1T [768 * 192];
__device__ float g_w2T [192 * 768];

// ---------------- helpers ----------------
__device__ __forceinline__ float to_tf32f(float x) {
    uint32_t r; asm("cvt.rna.tf32.f32 %0, %1;" : "=r"(r) : "f"(x));
    return __uint_as_float(r);
}
__device__ __forceinline__ void ldsm_x4(uint32_t* r, uint32_t addr) {
    asm volatile("ldmatrix.sync.aligned.m8n8.x4.shared.b16 {%0,%1,%2,%3}, [%4];"
        : "=r"(r[0]), "=r"(r[1]), "=r"(r[2]), "=r"(r[3]) : "r"(addr));
}
__device__ __forceinline__ void mma_tf32(float* c, const uint32_t* a,
                                         uint32_t b0, uint32_t b1) {
    asm volatile(
        "mma.sync.aligned.m16n8k8.row.col.f32.tf32.tf32.f32 "
        "{%0,%1,%2,%3}, {%4,%5,%6,%7}, {%8,%9}, {%0,%1,%2,%3};"
        : "+f"(c[0]), "+f"(c[1]), "+f"(c[2]), "+f"(c[3])
        : "r"(a[0]), "r"(a[1]), "r"(a[2]), "r"(a[3]), "r"(b0), "r"(b1));
}
__device__ __forceinline__ void cpa16(uint32_t dst, const void* src) {
    asm volatile("cp.async.cg.shared.global [%0], [%1], 16;" :: "r"(dst), "l"(src));
}

// ============================================================
// LayerNorm (+optional cyclic shift). Output tf32-rounded.
// ============================================================
template<bool SHIFT>
__global__ __launch_bounds__(256) void k_ln(
    const float* __restrict__ in, const float* __restrict__ g,
    const float* __restrict__ b, float* __restrict__ o)
{
    const int p    = blockIdx.x * 8 + (threadIdx.x >> 5);
    const int lane = threadIdx.x & 31;
    const float* src;
    if (SHIFT) {
        int bb = p / 3136, rem = p % 3136;
        int i = rem / 56, j = rem % 56;
        int si = i + 3; if (si >= 56) si -= 56;
        int sj = j + 3; if (sj >= 56) sj -= 56;
        src = in + ((size_t)(bb * 56 + si) * 56 + sj) * 192;
    } else {
        src = in + (size_t)p * 192;
    }
    float v[6]; float s = 0.f, s2 = 0.f;
    #pragma unroll
    for (int jj = 0; jj < 6; jj++) {
        v[jj] = src[lane + 32 * jj];
        s  += v[jj];
        s2 += v[jj] * v[jj];
    }
    #pragma unroll
    for (int off = 16; off > 0; off >>= 1) {
        s  += __shfl_xor_sync(0xffffffffu, s,  off);
        s2 += __shfl_xor_sync(0xffffffffu, s2, off);
    }
    float mean = s * (1.f / 192.f);
    float var  = s2 * (1.f / 192.f) - mean * mean;
    float inv  = rsqrtf(var + 1e-5f);
    float* dst = o + (size_t)p * 192;
    #pragma unroll
    for (int jj = 0; jj < 6; jj++) {
        int k = lane + 32 * jj;
        dst[k] = to_tf32f((v[jj] - mean) * inv * g[k] + b[k]);
    }
}

// ============================================================
// Weight transpose [K][N] -> [N][K], tf32-rounded.
// ============================================================
__global__ __launch_bounds__(256) void k_transpose(
    const float* __restrict__ W, float* __restrict__ WT, int K, int N)
{
    __shared__ float t[32][33];
    const int tx = threadIdx.x & 31, ty = threadIdx.x >> 5;
    const int bn = blockIdx.x * 32, bk = blockIdx.y * 32;
    #pragma unroll
    for (int i = 0; i < 4; i++)
        t[ty + 8 * i][tx] = W[(size_t)(bk + ty + 8 * i) * N + bn + tx];
    __syncthreads();
    #pragma unroll
    for (int i = 0; i < 4; i++)
        WT[(size_t)(bn + ty + 8 * i) * K + bk + tx] = to_tf32f(t[tx][ty + 8 * i]);
}

// ============================================================
// TF32 mma.sync GEMM: out[M,ND] = A[M,KD] @ WT[ND,KD]^T + epi
// block tile 256x96, BK=32, 256 threads = 8 warps (4M x 2N),
// warp tile 64x48 (4 mfrags x 6 nfrags). A+B frags via ldmatrix.
// cp.async double-buffered slabs (inputs pre-rounded to tf32).
// EPI 0: +bias, cols<192 *= 32^-0.5  (qkv)
// EPI 1: +bias, gelu, tf32-round     (mlp1)
// EPI 2: +bias, +res                 (proj / mlp2)
// ============================================================
#define AS 36                        // a_sm row stride (f32)
#define ASLAB (256 * AS)             // 9216 f32
#define BSLAB (96 * AS)              // 3456 f32
#define GEMM_SMEM ((2 * ASLAB + 2 * BSLAB) * 4)   // 101376 B

template<int EPI, int KD, int ND>
__global__ __launch_bounds__(256) void k_gemm(
    const float* __restrict__ A, const float* __restrict__ WT,
    const float* __restrict__ bias, const float* __restrict__ res,
    float* __restrict__ out)
{
    extern __shared__ float sm[];
    float* a_buf[2] = { sm,             sm + ASLAB };
    float* b_buf[2] = { sm + 2 * ASLAB, sm + 2 * ASLAB + BSLAB };

    const int tid   = threadIdx.x;
    const int lane  = tid & 31;
    const int wid   = tid >> 5;
    const int m0    = (wid >> 1) * 64;      // warp M origin in tile
    const int n0    = (wid & 1) * 48;       // warp N origin in tile
    const int row0  = blockIdx.x * 256;
    const int col0  = blockIdx.y * 96;

    float c[4][6][4];
    #pragma unroll
    for (int i = 0; i < 4; i++)
        #pragma unroll
        for (int j = 0; j < 6; j++)
            #pragma unroll
            for (int q = 0; q < 4; q++) c[i][j][q] = 0.f;

    auto load_slab = [&](int kc, int bi) {
        uint32_t ab = (uint32_t)__cvta_generic_to_shared(a_buf[bi]);
        uint32_t bb = (uint32_t)__cvta_generic_to_shared(b_buf[bi]);
        #pragma unroll
        for (int i = 0; i < 8; i++) {            // A: 256 rows x 8 chunks
            int idx = tid + 256 * i;
            int r = idx >> 3, ch = idx & 7;
            cpa16(ab + (uint32_t)(r * AS + ch * 4) * 4,
                  A + (size_t)(row0 + r) * KD + kc + ch * 4);
        }
        #pragma unroll
        for (int i = 0; i < 3; i++) {            // B: 96 rows x 8 chunks
            int idx = tid + 256 * i;
            int r = idx >> 3, ch = idx & 7;
            cpa16(bb + (uint32_t)(r * AS + ch * 4) * 4,
                  WT + (size_t)(col0 + r) * KD + kc + ch * 4);
        }
    };

    constexpr int S = KD / 32;
    load_slab(0, 0);
    asm volatile("cp.async.commit_group;");

    const int l15 = lane & 15;
    const int lhi = lane >> 4;
    const int bg  = lane >> 3;          // 0..3 matrix group for B ldsm
    const int br  = lane & 7;

    for (int s = 0; s < S; s++) {
        const int buf = s & 1;
        if (s + 1 < S) {
            load_slab((s + 1) * 32, buf ^ 1);
            asm volatile("cp.async.commit_group;");
            asm volatile("cp.async.wait_group 1;");
        } else {
            asm volatile("cp.async.wait_group 0;");
        }
        __syncthreads();

        const uint32_t a_base = (uint32_t)__cvta_generic_to_shared(a_buf[buf]);
        const uint32_t b_base = (uint32_t)__cvta_generic_to_shared(b_buf[buf]);

        #pragma unroll
        for (int ks = 0; ks < 4; ks++) {
            const int k0 = ks * 8;
            uint32_t a[4][4];
            #pragma unroll
            for (int i = 0; i < 4; i++) {
                uint32_t addr = a_base
                    + (uint32_t)(((m0 + 16 * i + l15) * AS + k0) * 4 + lhi * 16);
                ldsm_x4(a[i], addr);
            }
            uint32_t bf[3][4];
            #pragma unroll
            for (int jj = 0; jj < 3; jj++) {
                // m0: rows n..n+7 @k0..3 (b0 of frag 2jj), m1: @k0+4 (b1),
                // m2/m3: rows n+8..n+15 (frag 2jj+1)
                int nn = n0 + jj * 16 + ((bg >> 1) << 3) + br;
                int kk = k0 + ((bg & 1) << 2);
                uint32_t addr = b_base + (uint32_t)((nn * AS + kk) * 4);
                ldsm_x4(bf[jj], addr);
            }
            #pragma unroll
            for (int i = 0; i < 4; i++)
                #pragma unroll
                for (int j = 0; j < 6; j++)
                    mma_tf32(c[i][j], a[i], bf[j >> 1][(j & 1) * 2],
                                             bf[j >> 1][(j & 1) * 2 + 1]);
        }
        __syncthreads();   // protect buf before it is refilled next iter
    }

    // ---- epilogue ----
    const float qscale = 0.17677669529663687f;   // 32^-0.5
    #pragma unroll
    for (int i = 0; i < 4; i++) {
        #pragma unroll
        for (int j = 0; j < 6; j++) {
            int gc = col0 + n0 + 8 * j + (lane & 3) * 2;
            float2 bb = *(const float2*)&bias[gc];
            #pragma unroll
            for (int h = 0; h < 2; h++) {
                size_t r = (size_t)row0 + m0 + 16 * i + (lane >> 2) + 8 * h;
                float v0 = c[i][j][2 * h + 0] + bb.x;
                float v1 = c[i][j][2 * h + 1] + bb.y;
                if (EPI == 0) {
                    if (gc < 192) { v0 *= qscale; v1 *= qscale; }
                } else if (EPI == 1) {
                    v0 = to_tf32f(0.5f * v0 * (1.0f + erff(v0 * 0.70710678118654752f)));
                    v1 = to_tf32f(0.5f * v1 * (1.0f + erff(v1 * 0.70710678118654752f)));
                } else {
                    float2 rr = *(const float2*)&res[r * ND + gc];
                    v0 += rr.x; v1 += rr.y;
                }
                *(float2*)&out[r * ND + gc] = make_float2(v0, v1);
            }
        }
    }
}

// ============================================================
// Windowed attention (fp32), 1 block per (window, head).
// Output tf32-rounded (feeds proj GEMM).
// ============================================================
__global__ __launch_bounds__(128) void k_attn(const float* __restrict__ bias_table)
{
    __shared__ float q_sm[49][33];
    __shared__ float k_sm[49][33];
    __shared__ float v_sm[49][33];
    __shared__ float s_sm[49][50];

    const int w    = blockIdx.x;
    const int head = blockIdx.y;
    const int tid  = threadIdx.x;
    const int b    = w >> 6;
    const int wy   = (w >> 3) & 7;
    const int wx   = w & 7;

    for (int idx = tid; idx < 1568; idx += 128) {
        int n = idx >> 5, d = idx & 31;
        int ty = n / 7, tx = n - 7 * ty;
        size_t row = ((size_t)(b * 56 + wy * 7 + ty) * 56 + wx * 7 + tx);
        const float* base = g_qkv + row * 576 + head * 32 + d;
        q_sm[n][d] = base[0];
        k_sm[n][d] = base[192];
        v_sm[n][d] = base[384];
    }
    __syncthreads();

    for (int idx = tid; idx < 2401; idx += 128) {
        int n = idx / 49, m = idx - 49 * n;
        float a = 0.f;
        #pragma unroll
        for (int d = 0; d < 32; d++) a = fmaf(q_sm[n][d], k_sm[m][d], a);
        int i1 = n / 7, j1 = n - 7 * i1;
        int i2 = m / 7, j2 = m - 7 * i2;
        int bidx = (i1 - i2 + 6) * 13 + (j1 - j2 + 6);
        a += bias_table[bidx * 6 + head];
        s_sm[n][m] = a;
    }
    __syncthreads();

    const int lane = tid & 31, warp = tid >> 5;
    for (int n = warp; n < 49; n += 4) {
        float v0 = (lane < 49)      ? s_sm[n][lane]      : -1e30f;
        float v1 = (lane + 32 < 49) ? s_sm[n][lane + 32] : -1e30f;
        float mx = fmaxf(v0, v1);
        #pragma unroll
        for (int o = 16; o > 0; o >>= 1) mx = fmaxf(mx, __shfl_xor_sync(0xffffffffu, mx, o));
        float e0 = (lane < 49)      ? __expf(v0 - mx) : 0.f;
        float e1 = (lane + 32 < 49) ? __expf(v1 - mx) : 0.f;
        float sm = e0 + e1;
        #pragma unroll
        for (int o = 16; o > 0; o >>= 1) sm += __shfl_xor_sync(0xffffffffu, sm, o);
        float inv = 1.f / sm;
        if (lane < 49)      s_sm[n][lane]      = e0 * inv;
        if (lane + 32 < 49) s_sm[n][lane + 32] = e1 * inv;
    }
    __syncthreads();

    for (int idx = tid; idx < 1568; idx += 128) {
        int n = idx >> 5, d = idx & 31;
        float a = 0.f;
        #pragma unroll
        for (int m = 0; m < 49; m++) a = fmaf(s_sm[n][m], v_sm[m][d], a);
        int ty = n / 7, tx = n - 7 * ty;
        int oi = wy * 7 + ty + 3; if (oi >= 56) oi -= 56;
        int oj = wx * 7 + tx + 3; if (oj >= 56) oj -= 56;
        g_ao[((size_t)(b * 56 + oi) * 56 + oj) * 192 + head * 32 + d] = to_tf32f(a);
    }
}

// ============================================================
extern "C" void kernel_launch(void* const* d_in, const int* in_sizes, int n_in,
                              void* d_out, int out_size)
{
    (void)in_sizes; (void)n_in; (void)out_size;
    const float* x          = (const float*)d_in[0];
    const float* qkv_w      = (const float*)d_in[1];
    const float* qkv_b      = (const float*)d_in[2];
    const float* proj_w     = (const float*)d_in[3];
    const float* proj_b     = (const float*)d_in[4];
    const float* bias_table = (const float*)d_in[5];
    const float* n1g        = (const float*)d_in[6];
    const float* n1b        = (const float*)d_in[7];
    const float* n2g        = (const float*)d_in[8];
    const float* n2b        = (const float*)d_in[9];
    const float* w1         = (const float*)d_in[10];
    const float* b1         = (const float*)d_in[11];
    const float* w2         = (const float*)d_in[12];
    const float* b2         = (const float*)d_in[13];
    float* out = (float*)d_out;

    float* p_ln   = nullptr; cudaGetSymbolAddress((void**)&p_ln,   g_ln);
    float* p_qkv  = nullptr; cudaGetSymbolAddress((void**)&p_qkv,  g_qkv);
    float* p_ao   = nullptr; cudaGetSymbolAddress((void**)&p_ao,   g_ao);
    float* p_x2   = nullptr; cudaGetSymbolAddress((void**)&p_x2,   g_x2);
    float* p_h2   = nullptr; cudaGetSymbolAddress((void**)&p_h2,   g_h2);
    float* p_hid  = nullptr; cudaGetSymbolAddress((void**)&p_hid,  g_hid);
    float* p_qkvT = nullptr; cudaGetSymbolAddress((void**)&p_qkvT, g_qkvT);
    float* p_projT= nullptr; cudaGetSymbolAddress((void**)&p_projT,g_projT);
    float* p_w1T  = nullptr; cudaGetSymbolAddress((void**)&p_w1T,  g_w1T);
    float* p_w2T  = nullptr; cudaGetSymbolAddress((void**)&p_w2T,  g_w2T);

    cudaFuncSetAttribute(k_gemm<0,192,576>, cudaFuncAttributeMaxDynamicSharedMemorySize, GEMM_SMEM);
    cudaFuncSetAttribute(k_gemm<2,192,192>, cudaFuncAttributeMaxDynamicSharedMemorySize, GEMM_SMEM);
    cudaFuncSetAttribute(k_gemm<1,192,768>, cudaFuncAttributeMaxDynamicSharedMemorySize, GEMM_SMEM);
    cudaFuncSetAttribute(k_gemm<2,768,192>, cudaFuncAttributeMaxDynamicSharedMemorySize, GEMM_SMEM);

    // weight transposes (tf32-rounded)
    k_transpose<<<dim3(576/32, 192/32), 256>>>(qkv_w,  p_qkvT, 192, 576);
    k_transpose<<<dim3(192/32, 192/32), 256>>>(proj_w, p_projT,192, 192);
    k_transpose<<<dim3(768/32, 192/32), 256>>>(w1,     p_w1T,  192, 768);
    k_transpose<<<dim3(192/32, 768/32), 256>>>(w2,     p_w2T,  768, 192);

    // LN1 + shift
    k_ln<true><<<6272, 256>>>(x, n1g, n1b, p_ln);
    // QKV GEMM
    k_gemm<0,192,576><<<dim3(196, 6), 256, GEMM_SMEM>>>(p_ln, p_qkvT, qkv_b, nullptr, p_qkv);
    // attention
    k_attn<<<dim3(1024, 6), 128>>>(bias_table);
    // proj GEMM + residual
    k_gemm<2,192,192><<<dim3(196, 2), 256, GEMM_SMEM>>>(p_ao, p_projT, proj_b, x, p_x2);
    // LN2
    k_ln<false><<<6272, 256>>>(p_x2, n2g, n2b, p_h2);
    // MLP
    k_gemm<1,192,768><<<dim3(196, 8), 256, GEMM_SMEM>>>(p_h2, p_w1T, b1, nullptr, p_hid);
    k_gemm<2,768,192><<<dim3(196, 2), 256, GEMM_SMEM>>>(p_hid, p_w2T, b2, p_x2, out);
}

// round 7
// speedup vs baseline: 2.8937x; 1.1675x over previous
#include <cuda_runtime.h>
#include <math.h>
#include <stdint.h>

// ---------------- problem constants ----------------
#define TTOK 50176            // 16*56*56 tokens
#define CC   192
#define HID  768

// ---------------- scratch ----------------
__device__ float g_ln [(size_t)TTOK * CC];    // LN1(x), SHIFTED layout (tf32-rounded)
__device__ float g_qkv[(size_t)TTOK * 576];   // qkv, shifted layout, q pre-scaled, tf32-rounded
__device__ float g_ao [(size_t)TTOK * CC];    // attn out, UNSHIFTED (tf32-rounded)
__device__ float g_x2 [(size_t)TTOK * CC];    // residual stream after attn
__device__ float g_h2 [(size_t)TTOK * CC];    // LN2 out (tf32-rounded)
__device__ float g_hid[(size_t)TTOK * HID];   // MLP hidden (tf32-rounded)
// transposed (tf32-rounded) weights: WT[n][k]
__device__ float g_qkvT[576 * 192];
__device__ float g_projT[192 * 192];
__device__ float g_w1T [768 * 192];
__device__ float g_w2T [192 * 768];

// ---------------- helpers ----------------
__device__ __forceinline__ float to_tf32f(float x) {
    uint32_t r; asm("cvt.rna.tf32.f32 %0, %1;" : "=r"(r) : "f"(x));
    return __uint_as_float(r);
}
__device__ __forceinline__ void ldsm_x4(uint32_t* r, uint32_t addr) {
    asm volatile("ldmatrix.sync.aligned.m8n8.x4.shared.b16 {%0,%1,%2,%3}, [%4];"
        : "=r"(r[0]), "=r"(r[1]), "=r"(r[2]), "=r"(r[3]) : "r"(addr));
}
__device__ __forceinline__ void mma_tf32(float* c, const uint32_t* a,
                                         uint32_t b0, uint32_t b1) {
    asm volatile(
        "mma.sync.aligned.m16n8k8.row.col.f32.tf32.tf32.f32 "
        "{%0,%1,%2,%3}, {%4,%5,%6,%7}, {%8,%9}, {%0,%1,%2,%3};"
        : "+f"(c[0]), "+f"(c[1]), "+f"(c[2]), "+f"(c[3])
        : "r"(a[0]), "r"(a[1]), "r"(a[2]), "r"(a[3]), "r"(b0), "r"(b1));
}
__device__ __forceinline__ void cpa16(uint32_t dst, const void* src) {
    asm volatile("cp.async.cg.shared.global [%0], [%1], 16;" :: "r"(dst), "l"(src));
}

// ============================================================
// LayerNorm1 + cyclic shift. Output tf32-rounded.
// ============================================================
__global__ __launch_bounds__(256) void k_ln1(
    const float* __restrict__ in, const float* __restrict__ g,
    const float* __restrict__ b, float* __restrict__ o)
{
    const int p    = blockIdx.x * 8 + (threadIdx.x >> 5);
    const int lane = threadIdx.x & 31;
    int bb = p / 3136, rem = p % 3136;
    int i = rem / 56, j = rem % 56;
    int si = i + 3; if (si >= 56) si -= 56;
    int sj = j + 3; if (sj >= 56) sj -= 56;
    const float* src = in + ((size_t)(bb * 56 + si) * 56 + sj) * 192;
    float v[6]; float s = 0.f, s2 = 0.f;
    #pragma unroll
    for (int jj = 0; jj < 6; jj++) {
        v[jj] = src[lane + 32 * jj];
        s  += v[jj];
        s2 += v[jj] * v[jj];
    }
    #pragma unroll
    for (int off = 16; off > 0; off >>= 1) {
        s  += __shfl_xor_sync(0xffffffffu, s,  off);
        s2 += __shfl_xor_sync(0xffffffffu, s2, off);
    }
    float mean = s * (1.f / 192.f);
    float var  = s2 * (1.f / 192.f) - mean * mean;
    float inv  = rsqrtf(var + 1e-5f);
    float* dst = o + (size_t)p * 192;
    #pragma unroll
    for (int jj = 0; jj < 6; jj++) {
        int k = lane + 32 * jj;
        dst[k] = to_tf32f((v[jj] - mean) * inv * g[k] + b[k]);
    }
}

// ============================================================
// Weight transpose [K][N] -> [N][K], tf32-rounded.
// ============================================================
__global__ __launch_bounds__(256) void k_transpose(
    const float* __restrict__ W, float* __restrict__ WT, int K, int N)
{
    __shared__ float t[32][33];
    const int tx = threadIdx.x & 31, ty = threadIdx.x >> 5;
    const int bn = blockIdx.x * 32, bk = blockIdx.y * 32;
    #pragma unroll
    for (int i = 0; i < 4; i++)
        t[ty + 8 * i][tx] = W[(size_t)(bk + ty + 8 * i) * N + bn + tx];
    __syncthreads();
    #pragma unroll
    for (int i = 0; i < 4; i++)
        WT[(size_t)(bn + ty + 8 * i) * K + bk + tx] = to_tf32f(t[tx][ty + 8 * i]);
}

// ============================================================
// TF32 mma.sync GEMM: out[M,ND] = A[M,KD] @ WT[ND,KD]^T + epi
// block tile 256x96, BK=32, 8 warps (4M x 2N), warp tile 64x48.
// EPI 0: +bias, cols<192 *= 32^-0.5, tf32-round (qkv)
// EPI 1: +bias, gelu, tf32-round               (mlp1)
// EPI 2: +bias, +res                           (mlp2)
// ============================================================
#define AS 36
#define ASLAB (256 * AS)
#define BSLAB (96 * AS)
#define GEMM_SMEM ((2 * ASLAB + 2 * BSLAB) * 4)

template<int EPI, int KD, int ND>
__global__ __launch_bounds__(256) void k_gemm(
    const float* __restrict__ A, const float* __restrict__ WT,
    const float* __restrict__ bias, const float* __restrict__ res,
    float* __restrict__ out)
{
    extern __shared__ float sm[];
    float* a_buf[2] = { sm,             sm + ASLAB };
    float* b_buf[2] = { sm + 2 * ASLAB, sm + 2 * ASLAB + BSLAB };

    const int tid   = threadIdx.x;
    const int lane  = tid & 31;
    const int wid   = tid >> 5;
    const int m0    = (wid >> 1) * 64;
    const int n0    = (wid & 1) * 48;
    const int row0  = blockIdx.x * 256;
    const int col0  = blockIdx.y * 96;

    float c[4][6][4];
    #pragma unroll
    for (int i = 0; i < 4; i++)
        #pragma unroll
        for (int j = 0; j < 6; j++)
            #pragma unroll
            for (int q = 0; q < 4; q++) c[i][j][q] = 0.f;

    auto load_slab = [&](int kc, int bi) {
        uint32_t ab = (uint32_t)__cvta_generic_to_shared(a_buf[bi]);
        uint32_t bb = (uint32_t)__cvta_generic_to_shared(b_buf[bi]);
        #pragma unroll
        for (int i = 0; i < 8; i++) {
            int idx = tid + 256 * i;
            int r = idx >> 3, ch = idx & 7;
            cpa16(ab + (uint32_t)(r * AS + ch * 4) * 4,
                  A + (size_t)(row0 + r) * KD + kc + ch * 4);
        }
        #pragma unroll
        for (int i = 0; i < 3; i++) {
            int idx = tid + 256 * i;
            int r = idx >> 3, ch = idx & 7;
            cpa16(bb + (uint32_t)(r * AS + ch * 4) * 4,
                  WT + (size_t)(col0 + r) * KD + kc + ch * 4);
        }
    };

    constexpr int S = KD / 32;
    load_slab(0, 0);
    asm volatile("cp.async.commit_group;");

    const int l15 = lane & 15;
    const int lhi = lane >> 4;
    const int bg  = lane >> 3;
    const int br  = lane & 7;

    for (int s = 0; s < S; s++) {
        const int buf = s & 1;
        if (s + 1 < S) {
            load_slab((s + 1) * 32, buf ^ 1);
            asm volatile("cp.async.commit_group;");
            asm volatile("cp.async.wait_group 1;");
        } else {
            asm volatile("cp.async.wait_group 0;");
        }
        __syncthreads();

        const uint32_t a_base = (uint32_t)__cvta_generic_to_shared(a_buf[buf]);
        const uint32_t b_base = (uint32_t)__cvta_generic_to_shared(b_buf[buf]);

        #pragma unroll
        for (int ks = 0; ks < 4; ks++) {
            const int k0 = ks * 8;
            uint32_t a[4][4];
            #pragma unroll
            for (int i = 0; i < 4; i++) {
                uint32_t addr = a_base
                    + (uint32_t)(((m0 + 16 * i + l15) * AS + k0) * 4 + lhi * 16);
                ldsm_x4(a[i], addr);
            }
            uint32_t bf[3][4];
            #pragma unroll
            for (int jj = 0; jj < 3; jj++) {
                int nn = n0 + jj * 16 + ((bg >> 1) << 3) + br;
                int kk = k0 + ((bg & 1) << 2);
                uint32_t addr = b_base + (uint32_t)((nn * AS + kk) * 4);
                ldsm_x4(bf[jj], addr);
            }
            #pragma unroll
            for (int i = 0; i < 4; i++)
                #pragma unroll
                for (int j = 0; j < 6; j++)
                    mma_tf32(c[i][j], a[i], bf[j >> 1][(j & 1) * 2],
                                             bf[j >> 1][(j & 1) * 2 + 1]);
        }
        __syncthreads();
    }

    const float qscale = 0.17677669529663687f;
    #pragma unroll
    for (int i = 0; i < 4; i++) {
        #pragma unroll
        for (int j = 0; j < 6; j++) {
            int gc = col0 + n0 + 8 * j + (lane & 3) * 2;
            float2 bb = *(const float2*)&bias[gc];
            #pragma unroll
            for (int h = 0; h < 2; h++) {
                size_t r = (size_t)row0 + m0 + 16 * i + (lane >> 2) + 8 * h;
                float v0 = c[i][j][2 * h + 0] + bb.x;
                float v1 = c[i][j][2 * h + 1] + bb.y;
                if (EPI == 0) {
                    if (gc < 192) { v0 *= qscale; v1 *= qscale; }
                    v0 = to_tf32f(v0); v1 = to_tf32f(v1);
                } else if (EPI == 1) {
                    v0 = to_tf32f(0.5f * v0 * (1.0f + erff(v0 * 0.70710678118654752f)));
                    v1 = to_tf32f(0.5f * v1 * (1.0f + erff(v1 * 0.70710678118654752f)));
                } else {
                    float2 rr = *(const float2*)&res[r * ND + gc];
                    v0 += rr.x; v1 += rr.y;
                }
                *(float2*)&out[r * ND + gc] = make_float2(v0, v1);
            }
        }
    }
}

// ============================================================
// Proj GEMM (128x192 full-width tile) + residual + fused LN2.
// 8 warps (2M x 4N), warp tile 64x48. Writes x2 and h2.
// ============================================================
#define ASLAB_P (128 * AS)
#define BSLAB_P (192 * AS)
#define PROJ_SMEM (128 * 196 * 4)    // stage (100352) > gemm bufs (92160)

__global__ __launch_bounds__(256) void k_proj_ln(
    const float* __restrict__ A, const float* __restrict__ WT,
    const float* __restrict__ bias, const float* __restrict__ x,
    const float* __restrict__ g2, const float* __restrict__ b2,
    float* __restrict__ x2, float* __restrict__ h2)
{
    extern __shared__ float sm[];
    float* a_buf[2] = { sm,               sm + ASLAB_P };
    float* b_buf[2] = { sm + 2 * ASLAB_P, sm + 2 * ASLAB_P + BSLAB_P };
    float* stage = sm;   // aliased after mainloop

    const int tid  = threadIdx.x;
    const int lane = tid & 31;
    const int wid  = tid >> 5;
    const int m0   = (wid >> 2) * 64;
    const int n0   = (wid & 3) * 48;
    const int row0 = blockIdx.x * 128;

    float c[4][6][4];
    #pragma unroll
    for (int i = 0; i < 4; i++)
        #pragma unroll
        for (int j = 0; j < 6; j++)
            #pragma unroll
            for (int q = 0; q < 4; q++) c[i][j][q] = 0.f;

    auto load_slab = [&](int kc, int bi) {
        uint32_t ab = (uint32_t)__cvta_generic_to_shared(a_buf[bi]);
        uint32_t bb = (uint32_t)__cvta_generic_to_shared(b_buf[bi]);
        #pragma unroll
        for (int i = 0; i < 4; i++) {
            int idx = tid + 256 * i;
            int r = idx >> 3, ch = idx & 7;
            cpa16(ab + (uint32_t)(r * AS + ch * 4) * 4,
                  A + (size_t)(row0 + r) * 192 + kc + ch * 4);
        }
        #pragma unroll
        for (int i = 0; i < 6; i++) {
            int idx = tid + 256 * i;
            int r = idx >> 3, ch = idx & 7;
            cpa16(bb + (uint32_t)(r * AS + ch * 4) * 4,
                  WT + (size_t)r * 192 + kc + ch * 4);
        }
    };

    load_slab(0, 0);
    asm volatile("cp.async.commit_group;");

    const int l15 = lane & 15;
    const int lhi = lane >> 4;
    const int bg  = lane >> 3;
    const int br  = lane & 7;

    for (int s = 0; s < 6; s++) {
        const int buf = s & 1;
        if (s + 1 < 6) {
            load_slab((s + 1) * 32, buf ^ 1);
            asm volatile("cp.async.commit_group;");
            asm volatile("cp.async.wait_group 1;");
        } else {
            asm volatile("cp.async.wait_group 0;");
        }
        __syncthreads();

        const uint32_t a_base = (uint32_t)__cvta_generic_to_shared(a_buf[buf]);
        const uint32_t b_base = (uint32_t)__cvta_generic_to_shared(b_buf[buf]);

        #pragma unroll
        for (int ks = 0; ks < 4; ks++) {
            const int k0 = ks * 8;
            uint32_t a[4][4];
            #pragma unroll
            for (int i = 0; i < 4; i++) {
                uint32_t addr = a_base
                    + (uint32_t)(((m0 + 16 * i + l15) * AS + k0) * 4 + lhi * 16);
                ldsm_x4(a[i], addr);
            }
            uint32_t bf[3][4];
            #pragma unroll
            for (int jj = 0; jj < 3; jj++) {
                int nn = n0 + jj * 16 + ((bg >> 1) << 3) + br;
                int kk = k0 + ((bg & 1) << 2);
                uint32_t addr = b_base + (uint32_t)((nn * AS + kk) * 4);
                ldsm_x4(bf[jj], addr);
            }
            #pragma unroll
            for (int i = 0; i < 4; i++)
                #pragma unroll
                for (int j = 0; j < 6; j++)
                    mma_tf32(c[i][j], a[i], bf[j >> 1][(j & 1) * 2],
                                             bf[j >> 1][(j & 1) * 2 + 1]);
        }
        __syncthreads();
    }

    // epilogue: v = c + bias + x ; write x2 and stage
    #pragma unroll
    for (int i = 0; i < 4; i++) {
        #pragma unroll
        for (int j = 0; j < 6; j++) {
            int gc = n0 + 8 * j + (lane & 3) * 2;
            float2 bb = *(const float2*)&bias[gc];
            #pragma unroll
            for (int h = 0; h < 2; h++) {
                int lr = m0 + 16 * i + (lane >> 2) + 8 * h;
                size_t r = (size_t)row0 + lr;
                float2 rr = *(const float2*)&x[r * 192 + gc];
                float v0 = c[i][j][2 * h + 0] + bb.x + rr.x;
                float v1 = c[i][j][2 * h + 1] + bb.y + rr.y;
                *(float2*)&x2[r * 192 + gc] = make_float2(v0, v1);
                *(float2*)&stage[lr * 196 + gc] = make_float2(v0, v1);
            }
        }
    }
    __syncthreads();

    // LN2 over staged rows
    #pragma unroll 1
    for (int it = 0; it < 16; it++) {
        int lr = wid * 16 + it;
        float v[6]; float s = 0.f, s2 = 0.f;
        #pragma unroll
        for (int jj = 0; jj < 6; jj++) {
            v[jj] = stage[lr * 196 + lane + 32 * jj];
            s  += v[jj];
            s2 += v[jj] * v[jj];
        }
        #pragma unroll
        for (int off = 16; off > 0; off >>= 1) {
            s  += __shfl_xor_sync(0xffffffffu, s,  off);
            s2 += __shfl_xor_sync(0xffffffffu, s2, off);
        }
        float mean = s * (1.f / 192.f);
        float var  = s2 * (1.f / 192.f) - mean * mean;
        float inv  = rsqrtf(var + 1e-5f);
        size_t r = (size_t)row0 + lr;
        #pragma unroll
        for (int jj = 0; jj < 6; jj++) {
            int k = lane + 32 * jj;
            h2[r * 192 + k] = to_tf32f((v[jj] - mean) * inv * g2[k] + b2[k]);
        }
    }
}

// ============================================================
// Windowed attention via tf32 mma: 1 block per (window, head),
// 128 threads = 4 warps, each warp owns 16 query rows.
// s_sm stride 68: holds all 64 QK^T columns (59-wide was the
// R6 overflow bug).
// ============================================================
__global__ __launch_bounds__(128) void k_attn(const float* __restrict__ bias_table)
{
    __shared__ float q_sm[64][36];
    __shared__ float k_sm[64][36];
    __shared__ float v_t [32][60];    // V transposed: [dim][token]
    __shared__ float s_sm[64][68];
    __shared__ float bt[169];

    const int w    = blockIdx.x;
    const int head = blockIdx.y;
    const int tid  = threadIdx.x;
    const int lane = tid & 31;
    const int wid  = tid >> 5;
    const int b    = w >> 6;
    const int wy   = (w >> 3) & 7;
    const int wx   = w & 7;

    for (int i = tid; i < 169; i += 128) bt[i] = bias_table[i * 6 + head];

    for (int idx = tid; idx < 1568; idx += 128) {
        int n = idx >> 5, d = idx & 31;
        int ty = n / 7, tx = n - 7 * ty;
        size_t row = ((size_t)(b * 56 + wy * 7 + ty) * 56 + wx * 7 + tx);
        const float* base = g_qkv + row * 576 + head * 32 + d;
        q_sm[n][d] = base[0];
        k_sm[n][d] = base[192];
        v_t[d][n]  = base[384];
    }
    // zero pad: q/k rows 49..63 (cols 0..31), V pad tokens 49..55
    for (int idx = tid; idx < 480; idx += 128) {
        int rr = 49 + (idx >> 5), d = idx & 31;
        q_sm[rr][d] = 0.f;
        k_sm[rr][d] = 0.f;
    }
    for (int idx = tid; idx < 32 * 7; idx += 128)
        v_t[idx / 7][49 + idx % 7] = 0.f;
    __syncthreads();

    const int m0  = wid * 16;
    const int l15 = lane & 15, lhi = lane >> 4;
    const int bg  = lane >> 3, br = lane & 7;
    const uint32_t qb = (uint32_t)__cvta_generic_to_shared(q_sm);
    const uint32_t kb = (uint32_t)__cvta_generic_to_shared(k_sm);
    const uint32_t sb = (uint32_t)__cvta_generic_to_shared(s_sm);
    const uint32_t vb = (uint32_t)__cvta_generic_to_shared(v_t);

    // ---- QK^T: warp rows m0..m0+15, cols 0..63 ----
    float c[8][4];
    #pragma unroll
    for (int j = 0; j < 8; j++)
        #pragma unroll
        for (int q = 0; q < 4; q++) c[j][q] = 0.f;

    #pragma unroll
    for (int ks = 0; ks < 4; ks++) {
        const int k0 = ks * 8;
        uint32_t a[4];
        ldsm_x4(a, qb + (uint32_t)(((m0 + l15) * 36 + k0) * 4 + lhi * 16));
        uint32_t bf[4][4];
        #pragma unroll
        for (int jj = 0; jj < 4; jj++) {
            int nn = jj * 16 + ((bg >> 1) << 3) + br;
            int kk = k0 + ((bg & 1) << 2);
            ldsm_x4(bf[jj], kb + (uint32_t)((nn * 36 + kk) * 4));
        }
        #pragma unroll
        for (int j = 0; j < 8; j++)
            mma_tf32(c[j], a, bf[j >> 1][(j & 1) * 2], bf[j >> 1][(j & 1) * 2 + 1]);
    }

    // store S + bias
    {
        const int nr = m0 + (lane >> 2);
        #pragma unroll
        for (int j = 0; j < 8; j++) {
            const int m = 8 * j + (lane & 3) * 2;
            #pragma unroll
            for (int h = 0; h < 2; h++) {
                const int n = nr + 8 * h;
                float v0 = c[j][2 * h + 0];
                float v1 = c[j][2 * h + 1];
                if (n < 49) {
                    int i1 = n / 7, j1 = n - 7 * i1;
                    if (m < 49) {
                        int i2 = m / 7, j2 = m - 7 * i2;
                        v0 += bt[(i1 - i2 + 6) * 13 + (j1 - j2 + 6)];
                    }
                    if (m + 1 < 49) {
                        int i2 = (m + 1) / 7, j2 = (m + 1) - 7 * i2;
                        v1 += bt[(i1 - i2 + 6) * 13 + (j1 - j2 + 6)];
                    }
                }
                *(float2*)&s_sm[n][m] = make_float2(v0, v1);
            }
        }
    }
    __syncthreads();

    // softmax (rows/cols 0..48), P rounded to tf32
    for (int n = wid; n < 49; n += 4) {
        float v0 = (lane < 49)      ? s_sm[n][lane]      : -1e30f;
        float v1 = (lane + 32 < 49) ? s_sm[n][lane + 32] : -1e30f;
        float mx = fmaxf(v0, v1);
        #pragma unroll
        for (int o = 16; o > 0; o >>= 1) mx = fmaxf(mx, __shfl_xor_sync(0xffffffffu, mx, o));
        float e0 = (lane < 49)      ? __expf(v0 - mx) : 0.f;
        float e1 = (lane + 32 < 49) ? __expf(v1 - mx) : 0.f;
        float smv = e0 + e1;
        #pragma unroll
        for (int o = 16; o > 0; o >>= 1) smv += __shfl_xor_sync(0xffffffffu, smv, o);
        float inv = 1.f / smv;
        if (lane < 49)      s_sm[n][lane]      = to_tf32f(e0 * inv);
        if (lane + 32 < 49) s_sm[n][lane + 32] = to_tf32f(e1 * inv);
    }
    // zero P pad cols 49..55 (rows 0..48) for the K=56 PV mma
    for (int idx = tid; idx < 49 * 7; idx += 128)
        s_sm[idx / 7][49 + idx % 7] = 0.f;
    __syncthreads();

    // ---- P @ V: warp rows m0..m0+15, cols 0..31, K=56 ----
    float o[4][4];
    #pragma unroll
    for (int j = 0; j < 4; j++)
        #pragma unroll
        for (int q = 0; q < 4; q++) o[j][q] = 0.f;

    #pragma unroll
    for (int ks = 0; ks < 7; ks++) {
        const int k0 = ks * 8;
        uint32_t a[4];
        ldsm_x4(a, sb + (uint32_t)(((m0 + l15) * 68 + k0) * 4 + lhi * 16));
        uint32_t bf[2][4];
        #pragma unroll
        for (int jj = 0; jj < 2; jj++) {
            int nn = jj * 16 + ((bg >> 1) << 3) + br;
            int kk = k0 + ((bg & 1) << 2);
            ldsm_x4(bf[jj], vb + (uint32_t)((nn * 60 + kk) * 4));
        }
        #pragma unroll
        for (int j = 0; j < 4; j++)
            mma_tf32(o[j], a, bf[j >> 1][(j & 1) * 2], bf[j >> 1][(j & 1) * 2 + 1]);
    }

    // scatter to unshifted layout
    {
        const int nr = m0 + (lane >> 2);
        #pragma unroll
        for (int h = 0; h < 2; h++) {
            const int n = nr + 8 * h;
            if (n < 49) {
                int ty = n / 7, tx = n - 7 * ty;
                int oi = wy * 7 + ty + 3; if (oi >= 56) oi -= 56;
                int oj = wx * 7 + tx + 3; if (oj >= 56) oj -= 56;
                float* dst = g_ao + ((size_t)(b * 56 + oi) * 56 + oj) * 192 + head * 32;
                #pragma unroll
                for (int j = 0; j < 4; j++) {
                    int d = 8 * j + (lane & 3) * 2;
                    dst[d]     = to_tf32f(o[j][2 * h + 0]);
                    dst[d + 1] = to_tf32f(o[j][2 * h + 1]);
                }
            }
        }
    }
}

// ============================================================
extern "C" void kernel_launch(void* const* d_in, const int* in_sizes, int n_in,
                              void* d_out, int out_size)
{
    (void)in_sizes; (void)n_in; (void)out_size;
    const float* x          = (const float*)d_in[0];
    const float* qkv_w      = (const float*)d_in[1];
    const float* qkv_b      = (const float*)d_in[2];
    const float* proj_w     = (const float*)d_in[3];
    const float* proj_b     = (const float*)d_in[4];
    const float* bias_table = (const float*)d_in[5];
    const float* n1g        = (const float*)d_in[6];
    const float* n1b        = (const float*)d_in[7];
    const float* n2g        = (const float*)d_in[8];
    const float* n2b        = (const float*)d_in[9];
    const float* w1         = (const float*)d_in[10];
    const float* b1         = (const float*)d_in[11];
    const float* w2         = (const float*)d_in[12];
    const float* b2         = (const float*)d_in[13];
    float* out = (float*)d_out;

    float* p_ln   = nullptr; cudaGetSymbolAddress((void**)&p_ln,   g_ln);
    float* p_qkv  = nullptr; cudaGetSymbolAddress((void**)&p_qkv,  g_qkv);
    float* p_ao   = nullptr; cudaGetSymbolAddress((void**)&p_ao,   g_ao);
    float* p_x2   = nullptr; cudaGetSymbolAddress((void**)&p_x2,   g_x2);
    float* p_h2   = nullptr; cudaGetSymbolAddress((void**)&p_h2,   g_h2);
    float* p_hid  = nullptr; cudaGetSymbolAddress((void**)&p_hid,  g_hid);
    float* p_qkvT = nullptr; cudaGetSymbolAddress((void**)&p_qkvT, g_qkvT);
    float* p_projT= nullptr; cudaGetSymbolAddress((void**)&p_projT,g_projT);
    float* p_w1T  = nullptr; cudaGetSymbolAddress((void**)&p_w1T,  g_w1T);
    float* p_w2T  = nullptr; cudaGetSymbolAddress((void**)&p_w2T,  g_w2T);

    cudaFuncSetAttribute(k_gemm<0,192,576>, cudaFuncAttributeMaxDynamicSharedMemorySize, GEMM_SMEM);
    cudaFuncSetAttribute(k_gemm<1,192,768>, cudaFuncAttributeMaxDynamicSharedMemorySize, GEMM_SMEM);
    cudaFuncSetAttribute(k_gemm<2,768,192>, cudaFuncAttributeMaxDynamicSharedMemorySize, GEMM_SMEM);
    cudaFuncSetAttribute(k_proj_ln, cudaFuncAttributeMaxDynamicSharedMemorySize, PROJ_SMEM);

    // weight transposes (tf32-rounded)
    k_transpose<<<dim3(576/32, 192/32), 256>>>(qkv_w,  p_qkvT, 192, 576);
    k_transpose<<<dim3(192/32, 192/32), 256>>>(proj_w, p_projT,192, 192);
    k_transpose<<<dim3(768/32, 192/32), 256>>>(w1,     p_w1T,  192, 768);
    k_transpose<<<dim3(192/32, 768/32), 256>>>(w2,     p_w2T,  768, 192);

    // LN1 + shift
    k_ln1<<<6272, 256>>>(x, n1g, n1b, p_ln);
    // QKV GEMM (q pre-scaled, outputs tf32-rounded)
    k_gemm<0,192,576><<<dim3(196, 6), 256, GEMM_SMEM>>>(p_ln, p_qkvT, qkv_b, nullptr, p_qkv);
    // attention (tensor-core)
    k_attn<<<dim3(1024, 6), 128>>>(bias_table);
    // proj GEMM + residual + fused LN2
    k_proj_ln<<<392, 256, PROJ_SMEM>>>(p_ao, p_projT, proj_b, x, n2g, n2b, p_x2, p_h2);
    // MLP
    k_gemm<1,192,768><<<dim3(196, 8), 256, GEMM_SMEM>>>(p_h2, p_w1T, b1, nullptr, p_hid);
    k_gemm<2,768,192><<<dim3(196, 2), 256, GEMM_SMEM>>>(p_hid, p_w2T, b2, p_x2, out);
}

// round 13
// speedup vs baseline: 3.8976x; 1.3469x over previous
#include <cuda_runtime.h>
#include <cuda_fp16.h>
#include <math.h>
#include <stdint.h>

// ---------------- problem constants ----------------
#define TTOK 50176            // 16*56*56 tokens
#define CC   192
#define HID  768

// ---------------- scratch ----------------
__device__ __half g_ln [(size_t)TTOK * CC];    // LN1(x), SHIFTED layout, fp16
__device__ __half g_qkv[(size_t)TTOK * 576];   // qkv, shifted layout, q pre-scaled, fp16
__device__ __half g_ao [(size_t)TTOK * CC];    // attn out, UNSHIFTED, fp16
__device__ float  g_x2 [(size_t)TTOK * CC];    // residual stream after attn (fp32)
__device__ __half g_h2 [(size_t)TTOK * CC];    // LN2 out, fp16
__device__ __half g_hid[(size_t)TTOK * HID];   // MLP hidden, fp16
// transposed fp16 weights: WT[n][k]
__device__ __half g_qkvT[576 * 192];
__device__ __half g_projT[192 * 192];
__device__ __half g_w1T [768 * 192];
__device__ __half g_w2T [192 * 768];

// ---------------- helpers ----------------
__device__ __forceinline__ void ldsm_x4(uint32_t* r, uint32_t addr) {
    asm volatile("ldmatrix.sync.aligned.m8n8.x4.shared.b16 {%0,%1,%2,%3}, [%4];"
        : "=r"(r[0]), "=r"(r[1]), "=r"(r[2]), "=r"(r[3]) : "r"(addr));
}
__device__ __forceinline__ void mma_f16(float* c, const uint32_t* a,
                                        uint32_t b0, uint32_t b1) {
    asm volatile(
        "mma.sync.aligned.m16n8k16.row.col.f32.f16.f16.f32 "
        "{%0,%1,%2,%3}, {%4,%5,%6,%7}, {%8,%9}, {%0,%1,%2,%3};"
        : "+f"(c[0]), "+f"(c[1]), "+f"(c[2]), "+f"(c[3])
        : "r"(a[0]), "r"(a[1]), "r"(a[2]), "r"(a[3]), "r"(b0), "r"(b1));
}
__device__ __forceinline__ void cpa16(uint32_t dst, const void* src) {
    asm volatile("cp.async.cg.shared.global [%0], [%1], 16;" :: "r"(dst), "l"(src));
}

// ============================================================
// LayerNorm1 + cyclic shift. Output fp16.
// ============================================================
__global__ __launch_bounds__(256) void k_ln1(
    const float* __restrict__ in, const float* __restrict__ g,
    const float* __restrict__ b, __half* __restrict__ o)
{
    const int p    = blockIdx.x * 8 + (threadIdx.x >> 5);
    const int lane = threadIdx.x & 31;
    int bb = p / 3136, rem = p % 3136;
    int i = rem / 56, j = rem % 56;
    int si = i + 3; if (si >= 56) si -= 56;
    int sj = j + 3; if (sj >= 56) sj -= 56;
    const float* src = in + ((size_t)(bb * 56 + si) * 56 + sj) * 192;
    float v[6]; float s = 0.f, s2 = 0.f;
    #pragma unroll
    for (int jj = 0; jj < 6; jj++) {
        v[jj] = src[lane + 32 * jj];
        s  += v[jj];
        s2 += v[jj] * v[jj];
    }
    #pragma unroll
    for (int off = 16; off > 0; off >>= 1) {
        s  += __shfl_xor_sync(0xffffffffu, s,  off);
        s2 += __shfl_xor_sync(0xffffffffu, s2, off);
    }
    float mean = s * (1.f / 192.f);
    float var  = s2 * (1.f / 192.f) - mean * mean;
    float inv  = rsqrtf(var + 1e-5f);
    __half* dst = o + (size_t)p * 192;
    #pragma unroll
    for (int jj = 0; jj < 6; jj++) {
        int k = lane + 32 * jj;
        dst[k] = __float2half_rn((v[jj] - mean) * inv * g[k] + b[k]);
    }
}

// ============================================================
// Weight transpose [K][N] -> [N][K], fp16 output.
// ============================================================
__global__ __launch_bounds__(256) void k_transpose(
    const float* __restrict__ W, __half* __restrict__ WT, int K, int N)
{
    __shared__ float t[32][33];
    const int tx = threadIdx.x & 31, ty = threadIdx.x >> 5;
    const int bn = blockIdx.x * 32, bk = blockIdx.y * 32;
    #pragma unroll
    for (int i = 0; i < 4; i++)
        t[ty + 8 * i][tx] = W[(size_t)(bk + ty + 8 * i) * N + bn + tx];
    __syncthreads();
    #pragma unroll
    for (int i = 0; i < 4; i++)
        WT[(size_t)(bn + ty + 8 * i) * K + bk + tx] = __float2half_rn(t[tx][ty + 8 * i]);
}

// ============================================================
// FP16 mma.sync GEMM: out[M,ND] = A[M,KD] @ WT[ND,KD]^T + epi
// block tile 256x96, BK=32 halfs, 8 warps (4M x 2N), warp tile
// 64x48 (4 mfrags x 6 nfrags of m16n8k16).
// EPI 0: +bias, cols<192 *= 32^-0.5, out fp16 (qkv)
// EPI 1: +bias, gelu, out fp16             (mlp1)
// EPI 2: +bias, +res fp32, out fp32        (mlp2)
// ============================================================
#define AS 40                          // halfs per smem row (80 B)
#define ASLAB (256 * AS)               // halfs
#define BSLAB (96 * AS)
#define GEMM_SMEM ((2 * ASLAB + 2 * BSLAB) * 2)   // 56320 B

template<int EPI, int KD, int ND, typename OutT>
__global__ __launch_bounds__(256) void k_gemm(
    const __half* __restrict__ A, const __half* __restrict__ WT,
    const float* __restrict__ bias, const float* __restrict__ res,
    OutT* __restrict__ out)
{
    extern __shared__ __half hsm[];
    __half* a_buf[2] = { hsm,             hsm + ASLAB };
    __half* b_buf[2] = { hsm + 2 * ASLAB, hsm + 2 * ASLAB + BSLAB };

    const int tid   = threadIdx.x;
    const int lane  = tid & 31;
    const int wid   = tid >> 5;
    const int m0    = (wid >> 1) * 64;
    const int n0    = (wid & 1) * 48;
    const int row0  = blockIdx.x * 256;
    const int col0  = blockIdx.y * 96;

    float c[4][6][4];
    #pragma unroll
    for (int i = 0; i < 4; i++)
        #pragma unroll
        for (int j = 0; j < 6; j++)
            #pragma unroll
            for (int q = 0; q < 4; q++) c[i][j][q] = 0.f;

    auto load_slab = [&](int kc, int bi) {
        uint32_t ab = (uint32_t)__cvta_generic_to_shared(a_buf[bi]);
        uint32_t bb = (uint32_t)__cvta_generic_to_shared(b_buf[bi]);
        #pragma unroll
        for (int i = 0; i < 4; i++) {              // A: 256 rows x 4 chunks
            int idx = tid + 256 * i;
            int r = idx >> 2, ch = idx & 3;
            cpa16(ab + (uint32_t)(r * AS + ch * 8) * 2,
                  A + (size_t)(row0 + r) * KD + kc + ch * 8);
        }
        #pragma unroll
        for (int i = 0; i < 2; i++) {              // B: 96 rows x 4 chunks
            int idx = tid + 256 * i;
            if (idx < 384) {
                int r = idx >> 2, ch = idx & 3;
                cpa16(bb + (uint32_t)(r * AS + ch * 8) * 2,
                      WT + (size_t)(col0 + r) * KD + kc + ch * 8);
            }
        }
    };

    constexpr int S = KD / 32;
    load_slab(0, 0);
    asm volatile("cp.async.commit_group;");

    const int l15 = lane & 15;
    const int lhi = lane >> 4;
    const int bnn = ((lane >> 4) & 1) * 8 + (lane & 7);   // B row offset
    const int bkk = ((lane >> 3) & 1) * 8;                // B col offset (halfs)

    for (int s = 0; s < S; s++) {
        const int buf = s & 1;
        if (s + 1 < S) {
            load_slab((s + 1) * 32, buf ^ 1);
            asm volatile("cp.async.commit_group;");
            asm volatile("cp.async.wait_group 1;");
        } else {
            asm volatile("cp.async.wait_group 0;");
        }
        __syncthreads();

        const uint32_t a_base = (uint32_t)__cvta_generic_to_shared(a_buf[buf]);
        const uint32_t b_base = (uint32_t)__cvta_generic_to_shared(b_buf[buf]);

        #pragma unroll
        for (int ks = 0; ks < 2; ks++) {
            const int k0 = ks * 16;
            uint32_t a[4][4];
            #pragma unroll
            for (int i = 0; i < 4; i++) {
                uint32_t addr = a_base
                    + (uint32_t)(((m0 + 16 * i + l15) * AS + k0) * 2 + lhi * 16);
                ldsm_x4(a[i], addr);
            }
            uint32_t bf[3][4];
            #pragma unroll
            for (int jj = 0; jj < 3; jj++) {
                int nn = n0 + jj * 16 + bnn;
                uint32_t addr = b_base + (uint32_t)((nn * AS + k0 + bkk) * 2);
                ldsm_x4(bf[jj], addr);
            }
            #pragma unroll
            for (int i = 0; i < 4; i++)
                #pragma unroll
                for (int j = 0; j < 6; j++)
                    mma_f16(c[i][j], a[i], bf[j >> 1][(j & 1) * 2],
                                            bf[j >> 1][(j & 1) * 2 + 1]);
        }
        __syncthreads();
    }

    const float qscale = 0.17677669529663687f;
    #pragma unroll
    for (int i = 0; i < 4; i++) {
        #pragma unroll
        for (int j = 0; j < 6; j++) {
            int gc = col0 + n0 + 8 * j + (lane & 3) * 2;
            float2 bb = *(const float2*)&bias[gc];
            #pragma unroll
            for (int h = 0; h < 2; h++) {
                size_t r = (size_t)row0 + m0 + 16 * i + (lane >> 2) + 8 * h;
                float v0 = c[i][j][2 * h + 0] + bb.x;
                float v1 = c[i][j][2 * h + 1] + bb.y;
                if (EPI == 0) {
                    if (gc < 192) { v0 *= qscale; v1 *= qscale; }
                    *(__half2*)&out[r * ND + gc] = __floats2half2_rn(v0, v1);
                } else if (EPI == 1) {
                    v0 = 0.5f * v0 * (1.0f + erff(v0 * 0.70710678118654752f));
                    v1 = 0.5f * v1 * (1.0f + erff(v1 * 0.70710678118654752f));
                    *(__half2*)&out[r * ND + gc] = __floats2half2_rn(v0, v1);
                } else {
                    float2 rr = *(const float2*)&res[r * ND + gc];
                    v0 += rr.x; v1 += rr.y;
                    *(float2*)&out[r * ND + gc] = make_float2(v0, v1);
                }
            }
        }
    }
}

// ============================================================
// Proj GEMM (128x192 full-width tile) + residual + fused LN2.
// 8 warps (2M x 4N), warp tile 64x48. Writes x2 (fp32), h2 (fp16).
// ============================================================
#define ASLAB_P (128 * AS)
#define BSLAB_P (192 * AS)
#define PROJ_SMEM (128 * 196 * 4)    // fp32 stage dominates (100352 B)

__global__ __launch_bounds__(256) void k_proj_ln(
    const __half* __restrict__ A, const __half* __restrict__ WT,
    const float* __restrict__ bias, const float* __restrict__ x,
    const float* __restrict__ g2, const float* __restrict__ b2,
    float* __restrict__ x2, __half* __restrict__ h2)
{
    extern __shared__ float sm[];
    __half* hsm = (__half*)sm;
    __half* a_buf[2] = { hsm,               hsm + ASLAB_P };
    __half* b_buf[2] = { hsm + 2 * ASLAB_P, hsm + 2 * ASLAB_P + BSLAB_P };
    float* stage = sm;   // aliased after mainloop

    const int tid  = threadIdx.x;
    const int lane = tid & 31;
    const int wid  = tid >> 5;
    const int m0   = (wid >> 2) * 64;
    const int n0   = (wid & 3) * 48;
    const int row0 = blockIdx.x * 128;

    float c[4][6][4];
    #pragma unroll
    for (int i = 0; i < 4; i++)
        #pragma unroll
        for (int j = 0; j < 6; j++)
            #pragma unroll
            for (int q = 0; q < 4; q++) c[i][j][q] = 0.f;

    auto load_slab = [&](int kc, int bi) {
        uint32_t ab = (uint32_t)__cvta_generic_to_shared(a_buf[bi]);
        uint32_t bb = (uint32_t)__cvta_generic_to_shared(b_buf[bi]);
        #pragma unroll
        for (int i = 0; i < 2; i++) {              // A: 128 rows x 4 chunks
            int idx = tid + 256 * i;
            int r = idx >> 2, ch = idx & 3;
            cpa16(ab + (uint32_t)(r * AS + ch * 8) * 2,
                  A + (size_t)(row0 + r) * 192 + kc + ch * 8);
        }
        #pragma unroll
        for (int i = 0; i < 3; i++) {              // B: 192 rows x 4 chunks
            int idx = tid + 256 * i;
            int r = idx >> 2, ch = idx & 3;
            cpa16(bb + (uint32_t)(r * AS + ch * 8) * 2,
                  WT + (size_t)r * 192 + kc + ch * 8);
        }
    };

    load_slab(0, 0);
    asm volatile("cp.async.commit_group;");

    const int l15 = lane & 15;
    const int lhi = lane >> 4;
    const int bnn = ((lane >> 4) & 1) * 8 + (lane & 7);
    const int bkk = ((lane >> 3) & 1) * 8;

    for (int s = 0; s < 6; s++) {
        const int buf = s & 1;
        if (s + 1 < 6) {
            load_slab((s + 1) * 32, buf ^ 1);
            asm volatile("cp.async.commit_group;");
            asm volatile("cp.async.wait_group 1;");
        } else {
            asm volatile("cp.async.wait_group 0;");
        }
        __syncthreads();

        const uint32_t a_base = (uint32_t)__cvta_generic_to_shared(a_buf[buf]);
        const uint32_t b_base = (uint32_t)__cvta_generic_to_shared(b_buf[buf]);

        #pragma unroll
        for (int ks = 0; ks < 2; ks++) {
            const int k0 = ks * 16;
            uint32_t a[4][4];
            #pragma unroll
            for (int i = 0; i < 4; i++) {
                uint32_t addr = a_base
                    + (uint32_t)(((m0 + 16 * i + l15) * AS + k0) * 2 + lhi * 16);
                ldsm_x4(a[i], addr);
            }
            uint32_t bf[3][4];
            #pragma unroll
            for (int jj = 0; jj < 3; jj++) {
                int nn = n0 + jj * 16 + bnn;
                uint32_t addr = b_base + (uint32_t)((nn * AS + k0 + bkk) * 2);
                ldsm_x4(bf[jj], addr);
            }
            #pragma unroll
            for (int i = 0; i < 4; i++)
                #pragma unroll
                for (int j = 0; j < 6; j++)
                    mma_f16(c[i][j], a[i], bf[j >> 1][(j & 1) * 2],
                                            bf[j >> 1][(j & 1) * 2 + 1]);
        }
        __syncthreads();
    }

    // epilogue: v = c + bias + x ; write x2 (fp32) and stage
    #pragma unroll
    for (int i = 0; i < 4; i++) {
        #pragma unroll
        for (int j = 0; j < 6; j++) {
            int gc = n0 + 8 * j + (lane & 3) * 2;
            float2 bb = *(const float2*)&bias[gc];
            #pragma unroll
            for (int h = 0; h < 2; h++) {
                int lr = m0 + 16 * i + (lane >> 2) + 8 * h;
                size_t r = (size_t)row0 + lr;
                float2 rr = *(const float2*)&x[r * 192 + gc];
                float v0 = c[i][j][2 * h + 0] + bb.x + rr.x;
                float v1 = c[i][j][2 * h + 1] + bb.y + rr.y;
                *(float2*)&x2[r * 192 + gc] = make_float2(v0, v1);
                *(float2*)&stage[lr * 196 + gc] = make_float2(v0, v1);
            }
        }
    }
    __syncthreads();

    // LN2 over staged rows -> h2 fp16
    #pragma unroll 1
    for (int it = 0; it < 16; it++) {
        int lr = wid * 16 + it;
        float v[6]; float s = 0.f, s2 = 0.f;
        #pragma unroll
        for (int jj = 0; jj < 6; jj++) {
            v[jj] = stage[lr * 196 + lane + 32 * jj];
            s  += v[jj];
            s2 += v[jj] * v[jj];
        }
        #pragma unroll
        for (int off = 16; off > 0; off >>= 1) {
            s  += __shfl_xor_sync(0xffffffffu, s,  off);
            s2 += __shfl_xor_sync(0xffffffffu, s2, off);
        }
        float mean = s * (1.f / 192.f);
        float var  = s2 * (1.f / 192.f) - mean * mean;
        float inv  = rsqrtf(var + 1e-5f);
        size_t r = (size_t)row0 + lr;
        #pragma unroll
        for (int jj = 0; jj < 6; jj++) {
            int k = lane + 32 * jj;
            h2[r * 192 + k] = __float2half_rn((v[jj] - mean) * inv * g2[k] + b2[k]);
        }
    }
}

// ============================================================
// Windowed attention via fp16 mma: 1 block per (window, head),
// 128 threads = 4 warps, each warp owns 16 query rows.
// ============================================================
__global__ __launch_bounds__(128) void k_attn(const float* __restrict__ bias_table)
{
    __shared__ __half q_sm[64][40];
    __shared__ __half k_sm[64][40];
    __shared__ __half v_t [32][72];   // V transposed: [dim][token], K=64 padded
    __shared__ float  s_sm[64][68];   // fp32 scores
    __shared__ __half p_sm[64][72];   // fp16 probabilities, K=64 padded
    __shared__ float  bt[169];

    const int w    = blockIdx.x;
    const int head = blockIdx.y;
    const int tid  = threadIdx.x;
    const int lane = tid & 31;
    const int wid  = tid >> 5;
    const int b    = w >> 6;
    const int wy   = (w >> 3) & 7;
    const int wx   = w & 7;

    for (int i = tid; i < 169; i += 128) bt[i] = bias_table[i * 6 + head];

    // load q/k/v (half2 granularity), v transposed
    for (int idx = tid; idx < 784; idx += 128) {
        int n = idx >> 4, dp = idx & 15;
        int ty = n / 7, tx = n - 7 * ty;
        size_t row = ((size_t)(b * 56 + wy * 7 + ty) * 56 + wx * 7 + tx);
        const __half2* base = (const __half2*)(g_qkv + row * 576 + head * 32) + dp;
        __half2 qv = base[0];
        __half2 kv = base[96];    // +192 halfs
        __half2 vv = base[192];   // +384 halfs
        *(__half2*)&q_sm[n][2 * dp] = qv;
        *(__half2*)&k_sm[n][2 * dp] = kv;
        v_t[2 * dp][n]     = __low2half(vv);
        v_t[2 * dp + 1][n] = __high2half(vv);
    }
    // zero pads: q/k rows 49..63 (cols 0..31), v_t cols 49..63
    for (int idx = tid; idx < 480; idx += 128) {
        int rr = 49 + (idx >> 5), d = idx & 31;
        q_sm[rr][d] = __float2half(0.f);
        k_sm[rr][d] = __float2half(0.f);
        v_t[d][49 + (idx % 15)] = __float2half(0.f);
    }
    __syncthreads();

    const int m0  = wid * 16;
    const int l15 = lane & 15, lhi = lane >> 4;
    const int bnn = ((lane >> 4) & 1) * 8 + (lane & 7);
    const int bkk = ((lane >> 3) & 1) * 8;
    const uint32_t qb = (uint32_t)__cvta_generic_to_shared(q_sm);
    const uint32_t kb = (uint32_t)__cvta_generic_to_shared(k_sm);
    const uint32_t pb = (uint32_t)__cvta_generic_to_shared(p_sm);
    const uint32_t vb = (uint32_t)__cvta_generic_to_shared(v_t);

    // ---- QK^T: warp rows m0..m0+15, cols 0..63, K=32 ----
    float c[8][4];
    #pragma unroll
    for (int j = 0; j < 8; j++)
        #pragma unroll
        for (int q = 0; q < 4; q++) c[j][q] = 0.f;

    #pragma unroll
    for (int ks = 0; ks < 2; ks++) {
        const int k0 = ks * 16;
        uint32_t a[4];
        ldsm_x4(a, qb + (uint32_t)(((m0 + l15) * 40 + k0) * 2 + lhi * 16));
        uint32_t bf[4][4];
        #pragma unroll
        for (int jj = 0; jj < 4; jj++) {
            int nn = jj * 16 + bnn;
            ldsm_x4(bf[jj], kb + (uint32_t)((nn * 40 + k0 + bkk) * 2));
        }
        #pragma unroll
        for (int j = 0; j < 8; j++)
            mma_f16(c[j], a, bf[j >> 1][(j & 1) * 2], bf[j >> 1][(j & 1) * 2 + 1]);
    }

    // store S + bias (fp32)
    {
        const int nr = m0 + (lane >> 2);
        #pragma unroll
        for (int j = 0; j < 8; j++) {
            const int m = 8 * j + (lane & 3) * 2;
            #pragma unroll
            for (int h = 0; h < 2; h++) {
                const int n = nr + 8 * h;
                float v0 = c[j][2 * h + 0];
                float v1 = c[j][2 * h + 1];
                if (n < 49) {
                    int i1 = n / 7, j1 = n - 7 * i1;
                    if (m < 49) {
                        int i2 = m / 7, j2 = m - 7 * i2;
                        v0 += bt[(i1 - i2 + 6) * 13 + (j1 - j2 + 6)];
                    }
                    if (m + 1 < 49) {
                        int i2 = (m + 1) / 7, j2 = (m + 1) - 7 * i2;
                        v1 += bt[(i1 - i2 + 6) * 13 + (j1 - j2 + 6)];
                    }
                }
                *(float2*)&s_sm[n][m] = make_float2(v0, v1);
            }
        }
    }
    __syncthreads();

    // softmax rows 0..48 -> p_sm fp16; zero all pad entries
    for (int n = wid; n < 49; n += 4) {
        float v0 = (lane < 49)      ? s_sm[n][lane]      : -1e30f;
        float v1 = (lane + 32 < 49) ? s_sm[n][lane + 32] : -1e30f;
        float mx = fmaxf(v0, v1);
        #pragma unroll
        for (int o = 16; o > 0; o >>= 1) mx = fmaxf(mx, __shfl_xor_sync(0xffffffffu, mx, o));
        float e0 = (lane < 49)      ? __expf(v0 - mx) : 0.f;
        float e1 = (lane + 32 < 49) ? __expf(v1 - mx) : 0.f;
        float smv = e0 + e1;
        #pragma unroll
        for (int o = 16; o > 0; o >>= 1) smv += __shfl_xor_sync(0xffffffffu, smv, o);
        float inv = 1.f / smv;
        if (lane < 49)      p_sm[n][lane]      = __float2half_rn(e0 * inv);
        if (lane + 32 < 49) p_sm[n][lane + 32] = __float2half_rn(e1 * inv);
    }
    // pads: rows 0..48 cols 49..63; rows 49..63 cols 0..63
    for (int idx = tid; idx < 49 * 15; idx += 128)
        p_sm[idx / 15][49 + idx % 15] = __float2half(0.f);
    for (int idx = tid; idx < 15 * 64; idx += 128)
        p_sm[49 + (idx >> 6)][idx & 63] = __float2half(0.f);
    __syncthreads();

    // ---- P @ V: warp rows m0..m0+15, cols 0..31, K=64 ----
    float o[4][4];
    #pragma unroll
    for (int j = 0; j < 4; j++)
        #pragma unroll
        for (int q = 0; q < 4; q++) o[j][q] = 0.f;

    #pragma unroll
    for (int ks = 0; ks < 4; ks++) {
        const int k0 = ks * 16;
        uint32_t a[4];
        ldsm_x4(a, pb + (uint32_t)(((m0 + l15) * 72 + k0) * 2 + lhi * 16));
        uint32_t bf[2][4];
        #pragma unroll
        for (int jj = 0; jj < 2; jj++) {
            int nn = jj * 16 + bnn;
            ldsm_x4(bf[jj], vb + (uint32_t)((nn * 72 + k0 + bkk) * 2));
        }
        #pragma unroll
        for (int j = 0; j < 4; j++)
            mma_f16(o[j], a, bf[j >> 1][(j & 1) * 2], bf[j >> 1][(j & 1) * 2 + 1]);
    }

    // scatter to unshifted layout (fp16)
    {
        const int nr = m0 + (lane >> 2);
        #pragma unroll
        for (int h = 0; h < 2; h++) {
            const int n = nr + 8 * h;
            if (n < 49) {
                int ty = n / 7, tx = n - 7 * ty;
                int oi = wy * 7 + ty + 3; if (oi >= 56) oi -= 56;
                int oj = wx * 7 + tx + 3; if (oj >= 56) oj -= 56;
                __half* dst = g_ao + ((size_t)(b * 56 + oi) * 56 + oj) * 192 + head * 32;
                #pragma unroll
                for (int j = 0; j < 4; j++) {
                    int d = 8 * j + (lane & 3) * 2;
                    *(__half2*)&dst[d] = __floats2half2_rn(o[j][2 * h + 0], o[j][2 * h + 1]);
                }
            }
        }
    }
}

// ============================================================
extern "C" void kernel_launch(void* const* d_in, const int* in_sizes, int n_in,
                              void* d_out, int out_size)
{
    (void)in_sizes; (void)n_in; (void)out_size;
    const float* x          = (const float*)d_in[0];
    const float* qkv_w      = (const float*)d_in[1];
    const float* qkv_b      = (const float*)d_in[2];
    const float* proj_w     = (const float*)d_in[3];
    const float* proj_b     = (const float*)d_in[4];
    const float* bias_table = (const float*)d_in[5];
    const float* n1g        = (const float*)d_in[6];
    const float* n1b        = (const float*)d_in[7];
    const float* n2g        = (const float*)d_in[8];
    const float* n2b        = (const float*)d_in[9];
    const float* w1         = (const float*)d_in[10];
    const float* b1         = (const float*)d_in[11];
    const float* w2         = (const float*)d_in[12];
    const float* b2         = (const float*)d_in[13];
    float* out = (float*)d_out;

    __half* p_ln   = nullptr; cudaGetSymbolAddress((void**)&p_ln,   g_ln);
    __half* p_qkv  = nullptr; cudaGetSymbolAddress((void**)&p_qkv,  g_qkv);
    __half* p_ao   = nullptr; cudaGetSymbolAddress((void**)&p_ao,   g_ao);
    float*  p_x2   = nullptr; cudaGetSymbolAddress((void**)&p_x2,   g_x2);
    __half* p_h2   = nullptr; cudaGetSymbolAddress((void**)&p_h2,   g_h2);
    __half* p_hid  = nullptr; cudaGetSymbolAddress((void**)&p_hid,  g_hid);
    __half* p_qkvT = nullptr; cudaGetSymbolAddress((void**)&p_qkvT, g_qkvT);
    __half* p_projT= nullptr; cudaGetSymbolAddress((void**)&p_projT,g_projT);
    __half* p_w1T  = nullptr; cudaGetSymbolAddress((void**)&p_w1T,  g_w1T);
    __half* p_w2T  = nullptr; cudaGetSymbolAddress((void**)&p_w2T,  g_w2T);

    cudaFuncSetAttribute(k_gemm<0,192,576,__half>, cudaFuncAttributeMaxDynamicSharedMemorySize, GEMM_SMEM);
    cudaFuncSetAttribute(k_gemm<1,192,768,__half>, cudaFuncAttributeMaxDynamicSharedMemorySize, GEMM_SMEM);
    cudaFuncSetAttribute(k_gemm<2,768,192,float>,  cudaFuncAttributeMaxDynamicSharedMemorySize, GEMM_SMEM);
    cudaFuncSetAttribute(k_proj_ln, cudaFuncAttributeMaxDynamicSharedMemorySize, PROJ_SMEM);

    // weight transposes (fp16)
    k_transpose<<<dim3(576/32, 192/32), 256>>>(qkv_w,  p_qkvT, 192, 576);
    k_transpose<<<dim3(192/32, 192/32), 256>>>(proj_w, p_projT,192, 192);
    k_transpose<<<dim3(768/32, 192/32), 256>>>(w1,     p_w1T,  192, 768);
    k_transpose<<<dim3(192/32, 768/32), 256>>>(w2,     p_w2T,  768, 192);

    // LN1 + shift
    k_ln1<<<6272, 256>>>(x, n1g, n1b, p_ln);
    // QKV GEMM (q pre-scaled, fp16 out)
    k_gemm<0,192,576,__half><<<dim3(196, 6), 256, GEMM_SMEM>>>(p_ln, p_qkvT, qkv_b, nullptr, p_qkv);
    // attention (fp16 tensor-core)
    k_attn<<<dim3(1024, 6), 128>>>(bias_table);
    // proj GEMM + residual + fused LN2
    k_proj_ln<<<392, 256, PROJ_SMEM>>>(p_ao, p_projT, proj_b, x, n2g, n2b, p_x2, p_h2);
    // MLP
    k_gemm<1,192,768,__half><<<dim3(196, 8), 256, GEMM_SMEM>>>(p_h2, p_w1T, b1, nullptr, p_hid);
    k_gemm<2,768,192,float><<<dim3(196, 2), 256, GEMM_SMEM>>>(p_hid, p_w2T, b2, p_x2, out);
}

// round 14
// speedup vs baseline: 4.5500x; 1.1674x over previous
#include <cuda_runtime.h>
#include <cuda_fp16.h>
#include <math.h>
#include <stdint.h>

// ---------------- problem constants ----------------
#define TTOK 50176            // 16*56*56 tokens
#define CC   192
#define HID  768

// ---------------- scratch ----------------
__device__ __half g_ln [(size_t)TTOK * CC];    // LN1(x), SHIFTED layout, fp16
__device__ __half g_qkv[(size_t)TTOK * 576];   // qkv, shifted layout, q pre-scaled, fp16
__device__ __half g_ao [(size_t)TTOK * CC];    // attn out, UNSHIFTED, fp16
__device__ float  g_x2 [(size_t)TTOK * CC];    // residual stream after attn (fp32)
__device__ __half g_h2 [(size_t)TTOK * CC];    // LN2 out, fp16
__device__ __half g_hid[(size_t)TTOK * HID];   // MLP hidden, fp16
// transposed fp16 weights: WT[n][k]
__device__ __half g_qkvT[576 * 192];
__device__ __half g_projT[192 * 192];
__device__ __half g_w1T [768 * 192];
__device__ __half g_w2T [192 * 768];

// ---------------- helpers ----------------
__device__ __forceinline__ void ldsm_x4(uint32_t* r, uint32_t addr) {
    asm volatile("ldmatrix.sync.aligned.m8n8.x4.shared.b16 {%0,%1,%2,%3}, [%4];"
        : "=r"(r[0]), "=r"(r[1]), "=r"(r[2]), "=r"(r[3]) : "r"(addr));
}
__device__ __forceinline__ void mma_f16(float* c, const uint32_t* a,
                                        uint32_t b0, uint32_t b1) {
    asm volatile(
        "mma.sync.aligned.m16n8k16.row.col.f32.f16.f16.f32 "
        "{%0,%1,%2,%3}, {%4,%5,%6,%7}, {%8,%9}, {%0,%1,%2,%3};"
        : "+f"(c[0]), "+f"(c[1]), "+f"(c[2]), "+f"(c[3])
        : "r"(a[0]), "r"(a[1]), "r"(a[2]), "r"(a[3]), "r"(b0), "r"(b1));
}
__device__ __forceinline__ void cpa16(uint32_t dst, const void* src) {
    asm volatile("cp.async.cg.shared.global [%0], [%1], 16;" :: "r"(dst), "l"(src));
}

// ============================================================
// LayerNorm1 + cyclic shift. Output fp16.
// ============================================================
__global__ __launch_bounds__(256) void k_ln1(
    const float* __restrict__ in, const float* __restrict__ g,
    const float* __restrict__ b, __half* __restrict__ o)
{
    const int p    = blockIdx.x * 8 + (threadIdx.x >> 5);
    const int lane = threadIdx.x & 31;
    int bb = p / 3136, rem = p % 3136;
    int i = rem / 56, j = rem % 56;
    int si = i + 3; if (si >= 56) si -= 56;
    int sj = j + 3; if (sj >= 56) sj -= 56;
    const float* src = in + ((size_t)(bb * 56 + si) * 56 + sj) * 192;
    float v[6]; float s = 0.f, s2 = 0.f;
    #pragma unroll
    for (int jj = 0; jj < 6; jj++) {
        v[jj] = src[lane + 32 * jj];
        s  += v[jj];
        s2 += v[jj] * v[jj];
    }
    #pragma unroll
    for (int off = 16; off > 0; off >>= 1) {
        s  += __shfl_xor_sync(0xffffffffu, s,  off);
        s2 += __shfl_xor_sync(0xffffffffu, s2, off);
    }
    float mean = s * (1.f / 192.f);
    float var  = s2 * (1.f / 192.f) - mean * mean;
    float inv  = rsqrtf(var + 1e-5f);
    __half* dst = o + (size_t)p * 192;
    #pragma unroll
    for (int jj = 0; jj < 6; jj++) {
        int k = lane + 32 * jj;
        dst[k] = __float2half_rn((v[jj] - mean) * inv * g[k] + b[k]);
    }
}

// ============================================================
// All 4 weight transposes in ONE launch. [K][N] -> [N][K], fp16.
// grid 432: [0,108) qkv, [108,144) proj, [144,288) w1, [288,432) w2
// ============================================================
__global__ __launch_bounds__(256) void k_transpose_all(
    const float* __restrict__ qkv_w, const float* __restrict__ proj_w,
    const float* __restrict__ w1,    const float* __restrict__ w2,
    __half* __restrict__ qkvT, __half* __restrict__ projT,
    __half* __restrict__ w1T,  __half* __restrict__ w2T)
{
    __shared__ float t[32][33];
    const int bid = blockIdx.x;
    const float* W; __half* WT; int K, N, bi;
    if (bid < 108)      { W = qkv_w;  WT = qkvT;  K = 192; N = 576; bi = bid; }
    else if (bid < 144) { W = proj_w; WT = projT; K = 192; N = 192; bi = bid - 108; }
    else if (bid < 288) { W = w1;     WT = w1T;   K = 192; N = 768; bi = bid - 144; }
    else                { W = w2;     WT = w2T;   K = 768; N = 192; bi = bid - 288; }
    const int nb = N / 32;
    const int bn = (bi % nb) * 32, bk = (bi / nb) * 32;
    const int tx = threadIdx.x & 31, ty = threadIdx.x >> 5;
    #pragma unroll
    for (int i = 0; i < 4; i++)
        t[ty + 8 * i][tx] = W[(size_t)(bk + ty + 8 * i) * N + bn + tx];
    __syncthreads();
    #pragma unroll
    for (int i = 0; i < 4; i++)
        WT[(size_t)(bn + ty + 8 * i) * K + bk + tx] = __float2half_rn(t[tx][ty + 8 * i]);
}

// ============================================================
// FP16 mma.sync GEMM: out[M,ND] = A[M,KD] @ WT[ND,KD]^T + epi
// block tile 128x96, BK=32 halfs, 4 warps (2M x 2N), warp tile
// 64x48 (4 mfrags x 6 nfrags of m16n8k16). 3 CTAs/SM target.
// EPI 0: +bias, cols<192 *= 32^-0.5, out fp16 (qkv)
// EPI 1: +bias, gelu, out fp16             (mlp1)
// EPI 2: +bias, +res fp32, out fp32        (mlp2)
// ============================================================
#define AS 40                          // halfs per smem row (80 B)
#define ASLAB (128 * AS)               // halfs
#define BSLAB (96 * AS)
#define GEMM_SMEM ((2 * ASLAB + 2 * BSLAB) * 2)   // 35840 B

template<int EPI, int KD, int ND, typename OutT>
__global__ __launch_bounds__(128, 3) void k_gemm(
    const __half* __restrict__ A, const __half* __restrict__ WT,
    const float* __restrict__ bias, const float* __restrict__ res,
    OutT* __restrict__ out)
{
    extern __shared__ __half hsm[];
    __half* a_buf[2] = { hsm,             hsm + ASLAB };
    __half* b_buf[2] = { hsm + 2 * ASLAB, hsm + 2 * ASLAB + BSLAB };

    const int tid   = threadIdx.x;
    const int lane  = tid & 31;
    const int wid   = tid >> 5;
    const int m0    = (wid >> 1) * 64;
    const int n0    = (wid & 1) * 48;
    const int row0  = blockIdx.x * 128;
    const int col0  = blockIdx.y * 96;

    float c[4][6][4];
    #pragma unroll
    for (int i = 0; i < 4; i++)
        #pragma unroll
        for (int j = 0; j < 6; j++)
            #pragma unroll
            for (int q = 0; q < 4; q++) c[i][j][q] = 0.f;

    auto load_slab = [&](int kc, int bi) {
        uint32_t ab = (uint32_t)__cvta_generic_to_shared(a_buf[bi]);
        uint32_t bb = (uint32_t)__cvta_generic_to_shared(b_buf[bi]);
        #pragma unroll
        for (int i = 0; i < 4; i++) {              // A: 128 rows x 4 chunks
            int idx = tid + 128 * i;
            int r = idx >> 2, ch = idx & 3;
            cpa16(ab + (uint32_t)(r * AS + ch * 8) * 2,
                  A + (size_t)(row0 + r) * KD + kc + ch * 8);
        }
        #pragma unroll
        for (int i = 0; i < 3; i++) {              // B: 96 rows x 4 chunks
            int idx = tid + 128 * i;
            int r = idx >> 2, ch = idx & 3;
            cpa16(bb + (uint32_t)(r * AS + ch * 8) * 2,
                  WT + (size_t)(col0 + r) * KD + kc + ch * 8);
        }
    };

    constexpr int S = KD / 32;
    load_slab(0, 0);
    asm volatile("cp.async.commit_group;");

    const int l15 = lane & 15;
    const int lhi = lane >> 4;
    const int bnn = ((lane >> 4) & 1) * 8 + (lane & 7);   // B row offset
    const int bkk = ((lane >> 3) & 1) * 8;                // B col offset (halfs)

    for (int s = 0; s < S; s++) {
        const int buf = s & 1;
        if (s + 1 < S) {
            load_slab((s + 1) * 32, buf ^ 1);
            asm volatile("cp.async.commit_group;");
            asm volatile("cp.async.wait_group 1;");
        } else {
            asm volatile("cp.async.wait_group 0;");
        }
        __syncthreads();

        const uint32_t a_base = (uint32_t)__cvta_generic_to_shared(a_buf[buf]);
        const uint32_t b_base = (uint32_t)__cvta_generic_to_shared(b_buf[buf]);

        #pragma unroll
        for (int ks = 0; ks < 2; ks++) {
            const int k0 = ks * 16;
            uint32_t a[4][4];
            #pragma unroll
            for (int i = 0; i < 4; i++) {
                uint32_t addr = a_base
                    + (uint32_t)(((m0 + 16 * i + l15) * AS + k0) * 2 + lhi * 16);
                ldsm_x4(a[i], addr);
            }
            uint32_t bf[3][4];
            #pragma unroll
            for (int jj = 0; jj < 3; jj++) {
                int nn = n0 + jj * 16 + bnn;
                uint32_t addr = b_base + (uint32_t)((nn * AS + k0 + bkk) * 2);
                ldsm_x4(bf[jj], addr);
            }
            #pragma unroll
            for (int i = 0; i < 4; i++)
                #pragma unroll
                for (int j = 0; j < 6; j++)
                    mma_f16(c[i][j], a[i], bf[j >> 1][(j & 1) * 2],
                                            bf[j >> 1][(j & 1) * 2 + 1]);
        }
        __syncthreads();
    }

    const float qscale = 0.17677669529663687f;
    #pragma unroll
    for (int i = 0; i < 4; i++) {
        #pragma unroll
        for (int j = 0; j < 6; j++) {
            int gc = col0 + n0 + 8 * j + (lane & 3) * 2;
            float2 bb = *(const float2*)&bias[gc];
            #pragma unroll
            for (int h = 0; h < 2; h++) {
                size_t r = (size_t)row0 + m0 + 16 * i + (lane >> 2) + 8 * h;
                float v0 = c[i][j][2 * h + 0] + bb.x;
                float v1 = c[i][j][2 * h + 1] + bb.y;
                if (EPI == 0) {
                    if (gc < 192) { v0 *= qscale; v1 *= qscale; }
                    *(__half2*)&out[r * ND + gc] = __floats2half2_rn(v0, v1);
                } else if (EPI == 1) {
                    v0 = 0.5f * v0 * (1.0f + erff(v0 * 0.70710678118654752f));
                    v1 = 0.5f * v1 * (1.0f + erff(v1 * 0.70710678118654752f));
                    *(__half2*)&out[r * ND + gc] = __floats2half2_rn(v0, v1);
                } else {
                    float2 rr = *(const float2*)&res[r * ND + gc];
                    v0 += rr.x; v1 += rr.y;
                    *(float2*)&out[r * ND + gc] = make_float2(v0, v1);
                }
            }
        }
    }
}

// ============================================================
// Proj GEMM (128x192 full-width tile) + residual + fused LN2.
// 8 warps (2M x 4N), warp tile 64x48. Writes x2 (fp32), h2 (fp16).
// ============================================================
#define ASLAB_P (128 * AS)
#define BSLAB_P (192 * AS)
#define PROJ_SMEM (128 * 196 * 4)    // fp32 stage dominates (100352 B)

__global__ __launch_bounds__(256) void k_proj_ln(
    const __half* __restrict__ A, const __half* __restrict__ WT,
    const float* __restrict__ bias, const float* __restrict__ x,
    const float* __restrict__ g2, const float* __restrict__ b2,
    float* __restrict__ x2, __half* __restrict__ h2)
{
    extern __shared__ float sm[];
    __half* hsm = (__half*)sm;
    __half* a_buf[2] = { hsm,               hsm + ASLAB_P };
    __half* b_buf[2] = { hsm + 2 * ASLAB_P, hsm + 2 * ASLAB_P + BSLAB_P };
    float* stage = sm;   // aliased after mainloop

    const int tid  = threadIdx.x;
    const int lane = tid & 31;
    const int wid  = tid >> 5;
    const int m0   = (wid >> 2) * 64;
    const int n0   = (wid & 3) * 48;
    const int row0 = blockIdx.x * 128;

    float c[4][6][4];
    #pragma unroll
    for (int i = 0; i < 4; i++)
        #pragma unroll
        for (int j = 0; j < 6; j++)
            #pragma unroll
            for (int q = 0; q < 4; q++) c[i][j][q] = 0.f;

    auto load_slab = [&](int kc, int bi) {
        uint32_t ab = (uint32_t)__cvta_generic_to_shared(a_buf[bi]);
        uint32_t bb = (uint32_t)__cvta_generic_to_shared(b_buf[bi]);
        #pragma unroll
        for (int i = 0; i < 2; i++) {              // A: 128 rows x 4 chunks
            int idx = tid + 256 * i;
            int r = idx >> 2, ch = idx & 3;
            cpa16(ab + (uint32_t)(r * AS + ch * 8) * 2,
                  A + (size_t)(row0 + r) * 192 + kc + ch * 8);
        }
        #pragma unroll
        for (int i = 0; i < 3; i++) {              // B: 192 rows x 4 chunks
            int idx = tid + 256 * i;
            int r = idx >> 2, ch = idx & 3;
            cpa16(bb + (uint32_t)(r * AS + ch * 8) * 2,
                  WT + (size_t)r * 192 + kc + ch * 8);
        }
    };

    load_slab(0, 0);
    asm volatile("cp.async.commit_group;");

    const int l15 = lane & 15;
    const int lhi = lane >> 4;
    const int bnn = ((lane >> 4) & 1) * 8 + (lane & 7);
    const int bkk = ((lane >> 3) & 1) * 8;

    for (int s = 0; s < 6; s++) {
        const int buf = s & 1;
        if (s + 1 < 6) {
            load_slab((s + 1) * 32, buf ^ 1);
            asm volatile("cp.async.commit_group;");
            asm volatile("cp.async.wait_group 1;");
        } else {
            asm volatile("cp.async.wait_group 0;");
        }
        __syncthreads();

        const uint32_t a_base = (uint32_t)__cvta_generic_to_shared(a_buf[buf]);
        const uint32_t b_base = (uint32_t)__cvta_generic_to_shared(b_buf[buf]);

        #pragma unroll
        for (int ks = 0; ks < 2; ks++) {
            const int k0 = ks * 16;
            uint32_t a[4][4];
            #pragma unroll
            for (int i = 0; i < 4; i++) {
                uint32_t addr = a_base
                    + (uint32_t)(((m0 + 16 * i + l15) * AS + k0) * 2 + lhi * 16);
                ldsm_x4(a[i], addr);
            }
            uint32_t bf[3][4];
            #pragma unroll
            for (int jj = 0; jj < 3; jj++) {
                int nn = n0 + jj * 16 + bnn;
                uint32_t addr = b_base + (uint32_t)((nn * AS + k0 + bkk) * 2);
                ldsm_x4(bf[jj], addr);
            }
            #pragma unroll
            for (int i = 0; i < 4; i++)
                #pragma unroll
                for (int j = 0; j < 6; j++)
                    mma_f16(c[i][j], a[i], bf[j >> 1][(j & 1) * 2],
                                            bf[j >> 1][(j & 1) * 2 + 1]);
        }
        __syncthreads();
    }

    // epilogue: v = c + bias + x ; write x2 (fp32) and stage
    #pragma unroll
    for (int i = 0; i < 4; i++) {
        #pragma unroll
        for (int j = 0; j < 6; j++) {
            int gc = n0 + 8 * j + (lane & 3) * 2;
            float2 bb = *(const float2*)&bias[gc];
            #pragma unroll
            for (int h = 0; h < 2; h++) {
                int lr = m0 + 16 * i + (lane >> 2) + 8 * h;
                size_t r = (size_t)row0 + lr;
                float2 rr = *(const float2*)&x[r * 192 + gc];
                float v0 = c[i][j][2 * h + 0] + bb.x + rr.x;
                float v1 = c[i][j][2 * h + 1] + bb.y + rr.y;
                *(float2*)&x2[r * 192 + gc] = make_float2(v0, v1);
                *(float2*)&stage[lr * 196 + gc] = make_float2(v0, v1);
            }
        }
    }
    __syncthreads();

    // LN2 over staged rows -> h2 fp16
    #pragma unroll 1
    for (int it = 0; it < 16; it++) {
        int lr = wid * 16 + it;
        float v[6]; float s = 0.f, s2 = 0.f;
        #pragma unroll
        for (int jj = 0; jj < 6; jj++) {
            v[jj] = stage[lr * 196 + lane + 32 * jj];
            s  += v[jj];
            s2 += v[jj] * v[jj];
        }
        #pragma unroll
        for (int off = 16; off > 0; off >>= 1) {
            s  += __shfl_xor_sync(0xffffffffu, s,  off);
            s2 += __shfl_xor_sync(0xffffffffu, s2, off);
        }
        float mean = s * (1.f / 192.f);
        float var  = s2 * (1.f / 192.f) - mean * mean;
        float inv  = rsqrtf(var + 1e-5f);
        size_t r = (size_t)row0 + lr;
        #pragma unroll
        for (int jj = 0; jj < 6; jj++) {
            int k = lane + 32 * jj;
            h2[r * 192 + k] = __float2half_rn((v[jj] - mean) * inv * g2[k] + b2[k]);
        }
    }
}

// ============================================================
// Windowed attention via fp16 mma: 1 block per (window, head),
// 128 threads = 4 warps, each warp owns 16 query rows.
// ============================================================
__global__ __launch_bounds__(128) void k_attn(const float* __restrict__ bias_table)
{
    __shared__ __half q_sm[64][40];
    __shared__ __half k_sm[64][40];
    __shared__ __half v_t [32][72];   // V transposed: [dim][token], K=64 padded
    __shared__ float  s_sm[64][68];   // fp32 scores
    __shared__ __half p_sm[64][72];   // fp16 probabilities, K=64 padded
    __shared__ float  bt[169];

    const int w    = blockIdx.x;
    const int head = blockIdx.y;
    const int tid  = threadIdx.x;
    const int lane = tid & 31;
    const int wid  = tid >> 5;
    const int b    = w >> 6;
    const int wy   = (w >> 3) & 7;
    const int wx   = w & 7;

    for (int i = tid; i < 169; i += 128) bt[i] = bias_table[i * 6 + head];

    // load q/k/v (half2 granularity), v transposed
    for (int idx = tid; idx < 784; idx += 128) {
        int n = idx >> 4, dp = idx & 15;
        int ty = n / 7, tx = n - 7 * ty;
        size_t row = ((size_t)(b * 56 + wy * 7 + ty) * 56 + wx * 7 + tx);
        const __half2* base = (const __half2*)(g_qkv + row * 576 + head * 32) + dp;
        __half2 qv = base[0];
        __half2 kv = base[96];    // +192 halfs
        __half2 vv = base[192];   // +384 halfs
        *(__half2*)&q_sm[n][2 * dp] = qv;
        *(__half2*)&k_sm[n][2 * dp] = kv;
        v_t[2 * dp][n]     = __low2half(vv);
        v_t[2 * dp + 1][n] = __high2half(vv);
    }
    // zero pads: q/k rows 49..63 (cols 0..31), v_t cols 49..63
    for (int idx = tid; idx < 480; idx += 128) {
        int rr = 49 + (idx >> 5), d = idx & 31;
        q_sm[rr][d] = __float2half(0.f);
        k_sm[rr][d] = __float2half(0.f);
        v_t[d][49 + (idx % 15)] = __float2half(0.f);
    }
    __syncthreads();

    const int m0  = wid * 16;
    const int l15 = lane & 15, lhi = lane >> 4;
    const int bnn = ((lane >> 4) & 1) * 8 + (lane & 7);
    const int bkk = ((lane >> 3) & 1) * 8;
    const uint32_t qb = (uint32_t)__cvta_generic_to_shared(q_sm);
    const uint32_t kb = (uint32_t)__cvta_generic_to_shared(k_sm);
    const uint32_t pb = (uint32_t)__cvta_generic_to_shared(p_sm);
    const uint32_t vb = (uint32_t)__cvta_generic_to_shared(v_t);

    // ---- QK^T: warp rows m0..m0+15, cols 0..63, K=32 ----
    float c[8][4];
    #pragma unroll
    for (int j = 0; j < 8; j++)
        #pragma unroll
        for (int q = 0; q < 4; q++) c[j][q] = 0.f;

    #pragma unroll
    for (int ks = 0; ks < 2; ks++) {
        const int k0 = ks * 16;
        uint32_t a[4];
        ldsm_x4(a, qb + (uint32_t)(((m0 + l15) * 40 + k0) * 2 + lhi * 16));
        uint32_t bf[4][4];
        #pragma unroll
        for (int jj = 0; jj < 4; jj++) {
            int nn = jj * 16 + bnn;
            ldsm_x4(bf[jj], kb + (uint32_t)((nn * 40 + k0 + bkk) * 2));
        }
        #pragma unroll
        for (int j = 0; j < 8; j++)
            mma_f16(c[j], a, bf[j >> 1][(j & 1) * 2], bf[j >> 1][(j & 1) * 2 + 1]);
    }

    // store S + bias (fp32)
    {
        const int nr = m0 + (lane >> 2);
        #pragma unroll
        for (int j = 0; j < 8; j++) {
            const int m = 8 * j + (lane & 3) * 2;
            #pragma unroll
            for (int h = 0; h < 2; h++) {
                const int n = nr + 8 * h;
                float v0 = c[j][2 * h + 0];
                float v1 = c[j][2 * h + 1];
                if (n < 49) {
                    int i1 = n / 7, j1 = n - 7 * i1;
                    if (m < 49) {
                        int i2 = m / 7, j2 = m - 7 * i2;
                        v0 += bt[(i1 - i2 + 6) * 13 + (j1 - j2 + 6)];
                    }
                    if (m + 1 < 49) {
                        int i2 = (m + 1) / 7, j2 = (m + 1) - 7 * i2;
                        v1 += bt[(i1 - i2 + 6) * 13 + (j1 - j2 + 6)];
                    }
                }
                *(float2*)&s_sm[n][m] = make_float2(v0, v1);
            }
        }
    }
    __syncthreads();

    // softmax rows 0..48 -> p_sm fp16; zero all pad entries
    for (int n = wid; n < 49; n += 4) {
        float v0 = (lane < 49)      ? s_sm[n][lane]      : -1e30f;
        float v1 = (lane + 32 < 49) ? s_sm[n][lane + 32] : -1e30f;
        float mx = fmaxf(v0, v1);
        #pragma unroll
        for (int o = 16; o > 0; o >>= 1) mx = fmaxf(mx, __shfl_xor_sync(0xffffffffu, mx, o));
        float e0 = (lane < 49)      ? __expf(v0 - mx) : 0.f;
        float e1 = (lane + 32 < 49) ? __expf(v1 - mx) : 0.f;
        float smv = e0 + e1;
        #pragma unroll
        for (int o = 16; o > 0; o >>= 1) smv += __shfl_xor_sync(0xffffffffu, smv, o);
        float inv = 1.f / smv;
        if (lane < 49)      p_sm[n][lane]      = __float2half_rn(e0 * inv);
        if (lane + 32 < 49) p_sm[n][lane + 32] = __float2half_rn(e1 * inv);
    }
    // pads: rows 0..48 cols 49..63; rows 49..63 cols 0..63
    for (int idx = tid; idx < 49 * 15; idx += 128)
        p_sm[idx / 15][49 + idx % 15] = __float2half(0.f);
    for (int idx = tid; idx < 15 * 64; idx += 128)
        p_sm[49 + (idx >> 6)][idx & 63] = __float2half(0.f);
    __syncthreads();

    // ---- P @ V: warp rows m0..m0+15, cols 0..31, K=64 ----
    float o[4][4];
    #pragma unroll
    for (int j = 0; j < 4; j++)
        #pragma unroll
        for (int q = 0; q < 4; q++) o[j][q] = 0.f;

    #pragma unroll
    for (int ks = 0; ks < 4; ks++) {
        const int k0 = ks * 16;
        uint32_t a[4];
        ldsm_x4(a, pb + (uint32_t)(((m0 + l15) * 72 + k0) * 2 + lhi * 16));
        uint32_t bf[2][4];
        #pragma unroll
        for (int jj = 0; jj < 2; jj++) {
            int nn = jj * 16 + bnn;
            ldsm_x4(bf[jj], vb + (uint32_t)((nn * 72 + k0 + bkk) * 2));
        }
        #pragma unroll
        for (int j = 0; j < 4; j++)
            mma_f16(o[j], a, bf[j >> 1][(j & 1) * 2], bf[j >> 1][(j & 1) * 2 + 1]);
    }

    // scatter to unshifted layout (fp16)
    {
        const int nr = m0 + (lane >> 2);
        #pragma unroll
        for (int h = 0; h < 2; h++) {
            const int n = nr + 8 * h;
            if (n < 49) {
                int ty = n / 7, tx = n - 7 * ty;
                int oi = wy * 7 + ty + 3; if (oi >= 56) oi -= 56;
                int oj = wx * 7 + tx + 3; if (oj >= 56) oj -= 56;
                __half* dst = g_ao + ((size_t)(b * 56 + oi) * 56 + oj) * 192 + head * 32;
                #pragma unroll
                for (int j = 0; j < 4; j++) {
                    int d = 8 * j + (lane & 3) * 2;
                    *(__half2*)&dst[d] = __floats2half2_rn(o[j][2 * h + 0], o[j][2 * h + 1]);
                }
            }
        }
    }
}

// ============================================================
extern "C" void kernel_launch(void* const* d_in, const int* in_sizes, int n_in,
                              void* d_out, int out_size)
{
    (void)in_sizes; (void)n_in; (void)out_size;
    const float* x          = (const float*)d_in[0];
    const float* qkv_w      = (const float*)d_in[1];
    const float* qkv_b      = (const float*)d_in[2];
    const float* proj_w     = (const float*)d_in[3];
    const float* proj_b     = (const float*)d_in[4];
    const float* bias_table = (const float*)d_in[5];
    const float* n1g        = (const float*)d_in[6];
    const float* n1b        = (const float*)d_in[7];
    const float* n2g        = (const float*)d_in[8];
    const float* n2b        = (const float*)d_in[9];
    const float* w1         = (const float*)d_in[10];
    const float* b1         = (const float*)d_in[11];
    const float* w2         = (const float*)d_in[12];
    const float* b2         = (const float*)d_in[13];
    float* out = (float*)d_out;

    __half* p_ln   = nullptr; cudaGetSymbolAddress((void**)&p_ln,   g_ln);
    __half* p_qkv  = nullptr; cudaGetSymbolAddress((void**)&p_qkv,  g_qkv);
    __half* p_ao   = nullptr; cudaGetSymbolAddress((void**)&p_ao,   g_ao);
    float*  p_x2   = nullptr; cudaGetSymbolAddress((void**)&p_x2,   g_x2);
    __half* p_h2   = nullptr; cudaGetSymbolAddress((void**)&p_h2,   g_h2);
    __half* p_hid  = nullptr; cudaGetSymbolAddress((void**)&p_hid,  g_hid);
    __half* p_qkvT = nullptr; cudaGetSymbolAddress((void**)&p_qkvT, g_qkvT);
    __half* p_projT= nullptr; cudaGetSymbolAddress((void**)&p_projT,g_projT);
    __half* p_w1T  = nullptr; cudaGetSymbolAddress((void**)&p_w1T,  g_w1T);
    __half* p_w2T  = nullptr; cudaGetSymbolAddress((void**)&p_w2T,  g_w2T);

    cudaFuncSetAttribute(k_gemm<0,192,576,__half>, cudaFuncAttributeMaxDynamicSharedMemorySize, GEMM_SMEM);
    cudaFuncSetAttribute(k_gemm<1,192,768,__half>, cudaFuncAttributeMaxDynamicSharedMemorySize, GEMM_SMEM);
    cudaFuncSetAttribute(k_gemm<2,768,192,float>,  cudaFuncAttributeMaxDynamicSharedMemorySize, GEMM_SMEM);
    cudaFuncSetAttribute(k_proj_ln, cudaFuncAttributeMaxDynamicSharedMemorySize, PROJ_SMEM);

    // all weight transposes in one launch (fp16)
    k_transpose_all<<<432, 256>>>(qkv_w, proj_w, w1, w2,
                                  p_qkvT, p_projT, p_w1T, p_w2T);

    // LN1 + shift
    k_ln1<<<6272, 256>>>(x, n1g, n1b, p_ln);
    // QKV GEMM (q pre-scaled, fp16 out)
    k_gemm<0,192,576,__half><<<dim3(392, 6), 128, GEMM_SMEM>>>(p_ln, p_qkvT, qkv_b, nullptr, p_qkv);
    // attention (fp16 tensor-core)
    k_attn<<<dim3(1024, 6), 128>>>(bias_table);
    // proj GEMM + residual + fused LN2
    k_proj_ln<<<392, 256, PROJ_SMEM>>>(p_ao, p_projT, proj_b, x, n2g, n2b, p_x2, p_h2);
    // MLP
    k_gemm<1,192,768,__half><<<dim3(392, 8), 128, GEMM_SMEM>>>(p_h2, p_w1T, b1, nullptr, p_hid);
    k_gemm<2,768,192,float><<<dim3(392, 2), 128, GEMM_SMEM>>>(p_hid, p_w2T, b2, p_x2, out);
}

// round 16
// speedup vs baseline: 5.2947x; 1.1637x over previous
#include <cuda_runtime.h>
#include <cuda_fp16.h>
#include <math.h>
#include <stdint.h>

// ---------------- problem constants ----------------
#define TTOK 50176            // 16*56*56 tokens
#define CC   192
#define HID  768

// ---------------- scratch ----------------
__device__ __half g_ln [(size_t)TTOK * CC];    // LN1(x), SHIFTED layout, fp16
__device__ __half g_qkv[(size_t)TTOK * 576];   // qkv, shifted layout, q pre-scaled, fp16
__device__ __half g_ao [(size_t)TTOK * CC];    // attn out, UNSHIFTED, fp16
__device__ float  g_x2 [(size_t)TTOK * CC];    // residual stream after attn (fp32)
__device__ __half g_h2 [(size_t)TTOK * CC];    // LN2 out, fp16
__device__ __half g_hid[(size_t)TTOK * HID];   // MLP hidden, fp16
// transposed fp16 weights: WT[n][k]
__device__ __half g_qkvT[576 * 192];
__device__ __half g_projT[192 * 192];
__device__ __half g_w1T [768 * 192];
__device__ __half g_w2T [192 * 768];

// ---------------- helpers ----------------
__device__ __forceinline__ uint32_t h2u(__half2 h) {
    uint32_t u; *(__half2*)&u = h; return u;
}
__device__ __forceinline__ void ldsm_x4(uint32_t* r, uint32_t addr) {
    asm volatile("ldmatrix.sync.aligned.m8n8.x4.shared.b16 {%0,%1,%2,%3}, [%4];"
        : "=r"(r[0]), "=r"(r[1]), "=r"(r[2]), "=r"(r[3]) : "r"(addr));
}
__device__ __forceinline__ void mma_f16(float* c, const uint32_t* a,
                                        uint32_t b0, uint32_t b1) {
    asm volatile(
        "mma.sync.aligned.m16n8k16.row.col.f32.f16.f16.f32 "
        "{%0,%1,%2,%3}, {%4,%5,%6,%7}, {%8,%9}, {%0,%1,%2,%3};"
        : "+f"(c[0]), "+f"(c[1]), "+f"(c[2]), "+f"(c[3])
        : "r"(a[0]), "r"(a[1]), "r"(a[2]), "r"(a[3]), "r"(b0), "r"(b1));
}
__device__ __forceinline__ void cpa16(uint32_t dst, const void* src) {
    asm volatile("cp.async.cg.shared.global [%0], [%1], 16;" :: "r"(dst), "l"(src));
}

// ============================================================
// LayerNorm1 + cyclic shift. Output fp16.
// ============================================================
__global__ __launch_bounds__(256) void k_ln1(
    const float* __restrict__ in, const float* __restrict__ g,
    const float* __restrict__ b, __half* __restrict__ o)
{
    const int p    = blockIdx.x * 8 + (threadIdx.x >> 5);
    const int lane = threadIdx.x & 31;
    int bb = p / 3136, rem = p % 3136;
    int i = rem / 56, j = rem % 56;
    int si = i + 3; if (si >= 56) si -= 56;
    int sj = j + 3; if (sj >= 56) sj -= 56;
    const float* src = in + ((size_t)(bb * 56 + si) * 56 + sj) * 192;
    float v[6]; float s = 0.f, s2 = 0.f;
    #pragma unroll
    for (int jj = 0; jj < 6; jj++) {
        v[jj] = src[lane + 32 * jj];
        s  += v[jj];
        s2 += v[jj] * v[jj];
    }
    #pragma unroll
    for (int off = 16; off > 0; off >>= 1) {
        s  += __shfl_xor_sync(0xffffffffu, s,  off);
        s2 += __shfl_xor_sync(0xffffffffu, s2, off);
    }
    float mean = s * (1.f / 192.f);
    float var  = s2 * (1.f / 192.f) - mean * mean;
    float inv  = rsqrtf(var + 1e-5f);
    __half* dst = o + (size_t)p * 192;
    #pragma unroll
    for (int jj = 0; jj < 6; jj++) {
        int k = lane + 32 * jj;
        dst[k] = __float2half_rn((v[jj] - mean) * inv * g[k] + b[k]);
    }
}

// ============================================================
// All 4 weight transposes in ONE launch. [K][N] -> [N][K], fp16.
// ============================================================
__global__ __launch_bounds__(256) void k_transpose_all(
    const float* __restrict__ qkv_w, const float* __restrict__ proj_w,
    const float* __restrict__ w1,    const float* __restrict__ w2,
    __half* __restrict__ qkvT, __half* __restrict__ projT,
    __half* __restrict__ w1T,  __half* __restrict__ w2T)
{
    __shared__ float t[32][33];
    const int bid = blockIdx.x;
    const float* W; __half* WT; int K, N, bi;
    if (bid < 108)      { W = qkv_w;  WT = qkvT;  K = 192; N = 576; bi = bid; }
    else if (bid < 144) { W = proj_w; WT = projT; K = 192; N = 192; bi = bid - 108; }
    else if (bid < 288) { W = w1;     WT = w1T;   K = 192; N = 768; bi = bid - 144; }
    else                { W = w2;     WT = w2T;   K = 768; N = 192; bi = bid - 288; }
    const int nb = N / 32;
    const int bn = (bi % nb) * 32, bk = (bi / nb) * 32;
    const int tx = threadIdx.x & 31, ty = threadIdx.x >> 5;
    #pragma unroll
    for (int i = 0; i < 4; i++)
        t[ty + 8 * i][tx] = W[(size_t)(bk + ty + 8 * i) * N + bn + tx];
    __syncthreads();
    #pragma unroll
    for (int i = 0; i < 4; i++)
        WT[(size_t)(bn + ty + 8 * i) * K + bk + tx] = __float2half_rn(t[tx][ty + 8 * i]);
}

// ============================================================
// FP16 mma.sync GEMM: out[M,ND] = A[M,KD] @ WT[ND,KD]^T + epi
// block tile 128x96, BK=32, 4 warps (2M x 2N), warp tile 64x48.
// ============================================================
#define AS 40                          // halfs per smem row (80 B)
#define ASLAB (128 * AS)
#define BSLAB (96 * AS)
#define GEMM_SMEM ((2 * ASLAB + 2 * BSLAB) * 2)   // 35840 B

template<int EPI, int KD, int ND, typename OutT>
__global__ __launch_bounds__(128, 3) void k_gemm(
    const __half* __restrict__ A, const __half* __restrict__ WT,
    const float* __restrict__ bias, const float* __restrict__ res,
    OutT* __restrict__ out)
{
    extern __shared__ __half hsm[];
    __half* a_buf[2] = { hsm,             hsm + ASLAB };
    __half* b_buf[2] = { hsm + 2 * ASLAB, hsm + 2 * ASLAB + BSLAB };

    const int tid   = threadIdx.x;
    const int lane  = tid & 31;
    const int wid   = tid >> 5;
    const int m0    = (wid >> 1) * 64;
    const int n0    = (wid & 1) * 48;
    const int row0  = blockIdx.x * 128;
    const int col0  = blockIdx.y * 96;

    float c[4][6][4];
    #pragma unroll
    for (int i = 0; i < 4; i++)
        #pragma unroll
        for (int j = 0; j < 6; j++)
            #pragma unroll
            for (int q = 0; q < 4; q++) c[i][j][q] = 0.f;

    auto load_slab = [&](int kc, int bi) {
        uint32_t ab = (uint32_t)__cvta_generic_to_shared(a_buf[bi]);
        uint32_t bb = (uint32_t)__cvta_generic_to_shared(b_buf[bi]);
        #pragma unroll
        for (int i = 0; i < 4; i++) {
            int idx = tid + 128 * i;
            int r = idx >> 2, ch = idx & 3;
            cpa16(ab + (uint32_t)(r * AS + ch * 8) * 2,
                  A + (size_t)(row0 + r) * KD + kc + ch * 8);
        }
        #pragma unroll
        for (int i = 0; i < 3; i++) {
            int idx = tid + 128 * i;
            int r = idx >> 2, ch = idx & 3;
            cpa16(bb + (uint32_t)(r * AS + ch * 8) * 2,
                  WT + (size_t)(col0 + r) * KD + kc + ch * 8);
        }
    };

    constexpr int S = KD / 32;
    load_slab(0, 0);
    asm volatile("cp.async.commit_group;");

    const int l15 = lane & 15;
    const int lhi = lane >> 4;
    const int bnn = ((lane >> 4) & 1) * 8 + (lane & 7);
    const int bkk = ((lane >> 3) & 1) * 8;

    for (int s = 0; s < S; s++) {
        const int buf = s & 1;
        if (s + 1 < S) {
            load_slab((s + 1) * 32, buf ^ 1);
            asm volatile("cp.async.commit_group;");
            asm volatile("cp.async.wait_group 1;");
        } else {
            asm volatile("cp.async.wait_group 0;");
        }
        __syncthreads();

        const uint32_t a_base = (uint32_t)__cvta_generic_to_shared(a_buf[buf]);
        const uint32_t b_base = (uint32_t)__cvta_generic_to_shared(b_buf[buf]);

        #pragma unroll
        for (int ks = 0; ks < 2; ks++) {
            const int k0 = ks * 16;
            uint32_t a[4][4];
            #pragma unroll
            for (int i = 0; i < 4; i++) {
                uint32_t addr = a_base
                    + (uint32_t)(((m0 + 16 * i + l15) * AS + k0) * 2 + lhi * 16);
                ldsm_x4(a[i], addr);
            }
            uint32_t bf[3][4];
            #pragma unroll
            for (int jj = 0; jj < 3; jj++) {
                int nn = n0 + jj * 16 + bnn;
                uint32_t addr = b_base + (uint32_t)((nn * AS + k0 + bkk) * 2);
                ldsm_x4(bf[jj], addr);
            }
            #pragma unroll
            for (int i = 0; i < 4; i++)
                #pragma unroll
                for (int j = 0; j < 6; j++)
                    mma_f16(c[i][j], a[i], bf[j >> 1][(j & 1) * 2],
                                            bf[j >> 1][(j & 1) * 2 + 1]);
        }
        __syncthreads();
    }

    const float qscale = 0.17677669529663687f;
    #pragma unroll
    for (int i = 0; i < 4; i++) {
        #pragma unroll
        for (int j = 0; j < 6; j++) {
            int gc = col0 + n0 + 8 * j + (lane & 3) * 2;
            float2 bb = *(const float2*)&bias[gc];
            #pragma unroll
            for (int h = 0; h < 2; h++) {
                size_t r = (size_t)row0 + m0 + 16 * i + (lane >> 2) + 8 * h;
                float v0 = c[i][j][2 * h + 0] + bb.x;
                float v1 = c[i][j][2 * h + 1] + bb.y;
                if (EPI == 0) {
                    if (gc < 192) { v0 *= qscale; v1 *= qscale; }
                    *(__half2*)&out[r * ND + gc] = __floats2half2_rn(v0, v1);
                } else if (EPI == 1) {
                    v0 = 0.5f * v0 * (1.0f + erff(v0 * 0.70710678118654752f));
                    v1 = 0.5f * v1 * (1.0f + erff(v1 * 0.70710678118654752f));
                    *(__half2*)&out[r * ND + gc] = __floats2half2_rn(v0, v1);
                } else {
                    float2 rr = *(const float2*)&res[r * ND + gc];
                    v0 += rr.x; v1 += rr.y;
                    *(float2*)&out[r * ND + gc] = make_float2(v0, v1);
                }
            }
        }
    }
}

// ============================================================
// Proj GEMM (128x192 full-width tile) + residual + fused LN2.
// ============================================================
#define ASLAB_P (128 * AS)
#define BSLAB_P (192 * AS)
#define PROJ_SMEM (128 * 196 * 4)

__global__ __launch_bounds__(256) void k_proj_ln(
    const __half* __restrict__ A, const __half* __restrict__ WT,
    const float* __restrict__ bias, const float* __restrict__ x,
    const float* __restrict__ g2, const float* __restrict__ b2,
    float* __restrict__ x2, __half* __restrict__ h2)
{
    extern __shared__ float sm[];
    __half* hsm = (__half*)sm;
    __half* a_buf[2] = { hsm,               hsm + ASLAB_P };
    __half* b_buf[2] = { hsm + 2 * ASLAB_P, hsm + 2 * ASLAB_P + BSLAB_P };
    float* stage = sm;

    const int tid  = threadIdx.x;
    const int lane = tid & 31;
    const int wid  = tid >> 5;
    const int m0   = (wid >> 2) * 64;
    const int n0   = (wid & 3) * 48;
    const int row0 = blockIdx.x * 128;

    float c[4][6][4];
    #pragma unroll
    for (int i = 0; i < 4; i++)
        #pragma unroll
        for (int j = 0; j < 6; j++)
            #pragma unroll
            for (int q = 0; q < 4; q++) c[i][j][q] = 0.f;

    auto load_slab = [&](int kc, int bi) {
        uint32_t ab = (uint32_t)__cvta_generic_to_shared(a_buf[bi]);
        uint32_t bb = (uint32_t)__cvta_generic_to_shared(b_buf[bi]);
        #pragma unroll
        for (int i = 0; i < 2; i++) {
            int idx = tid + 256 * i;
            int r = idx >> 2, ch = idx & 3;
            cpa16(ab + (uint32_t)(r * AS + ch * 8) * 2,
                  A + (size_t)(row0 + r) * 192 + kc + ch * 8);
        }
        #pragma unroll
        for (int i = 0; i < 3; i++) {
            int idx = tid + 256 * i;
            int r = idx >> 2, ch = idx & 3;
            cpa16(bb + (uint32_t)(r * AS + ch * 8) * 2,
                  WT + (size_t)r * 192 + kc + ch * 8);
        }
    };

    load_slab(0, 0);
    asm volatile("cp.async.commit_group;");

    const int l15 = lane & 15;
    const int lhi = lane >> 4;
    const int bnn = ((lane >> 4) & 1) * 8 + (lane & 7);
    const int bkk = ((lane >> 3) & 1) * 8;

    for (int s = 0; s < 6; s++) {
        const int buf = s & 1;
        if (s + 1 < 6) {
            load_slab((s + 1) * 32, buf ^ 1);
            asm volatile("cp.async.commit_group;");
            asm volatile("cp.async.wait_group 1;");
        } else {
            asm volatile("cp.async.wait_group 0;");
        }
        __syncthreads();

        const uint32_t a_base = (uint32_t)__cvta_generic_to_shared(a_buf[buf]);
        const uint32_t b_base = (uint32_t)__cvta_generic_to_shared(b_buf[buf]);

        #pragma unroll
        for (int ks = 0; ks < 2; ks++) {
            const int k0 = ks * 16;
            uint32_t a[4][4];
            #pragma unroll
            for (int i = 0; i < 4; i++) {
                uint32_t addr = a_base
                    + (uint32_t)(((m0 + 16 * i + l15) * AS + k0) * 2 + lhi * 16);
                ldsm_x4(a[i], addr);
            }
            uint32_t bf[3][4];
            #pragma unroll
            for (int jj = 0; jj < 3; jj++) {
                int nn = n0 + jj * 16 + bnn;
                uint32_t addr = b_base + (uint32_t)((nn * AS + k0 + bkk) * 2);
                ldsm_x4(bf[jj], addr);
            }
            #pragma unroll
            for (int i = 0; i < 4; i++)
                #pragma unroll
                for (int j = 0; j < 6; j++)
                    mma_f16(c[i][j], a[i], bf[j >> 1][(j & 1) * 2],
                                            bf[j >> 1][(j & 1) * 2 + 1]);
        }
        __syncthreads();
    }

    #pragma unroll
    for (int i = 0; i < 4; i++) {
        #pragma unroll
        for (int j = 0; j < 6; j++) {
            int gc = n0 + 8 * j + (lane & 3) * 2;
            float2 bb = *(const float2*)&bias[gc];
            #pragma unroll
            for (int h = 0; h < 2; h++) {
                int lr = m0 + 16 * i + (lane >> 2) + 8 * h;
                size_t r = (size_t)row0 + lr;
                float2 rr = *(const float2*)&x[r * 192 + gc];
                float v0 = c[i][j][2 * h + 0] + bb.x + rr.x;
                float v1 = c[i][j][2 * h + 1] + bb.y + rr.y;
                *(float2*)&x2[r * 192 + gc] = make_float2(v0, v1);
                *(float2*)&stage[lr * 196 + gc] = make_float2(v0, v1);
            }
        }
    }
    __syncthreads();

    #pragma unroll 1
    for (int it = 0; it < 16; it++) {
        int lr = wid * 16 + it;
        float v[6]; float s = 0.f, s2 = 0.f;
        #pragma unroll
        for (int jj = 0; jj < 6; jj++) {
            v[jj] = stage[lr * 196 + lane + 32 * jj];
            s  += v[jj];
            s2 += v[jj] * v[jj];
        }
        #pragma unroll
        for (int off = 16; off > 0; off >>= 1) {
            s  += __shfl_xor_sync(0xffffffffu, s,  off);
            s2 += __shfl_xor_sync(0xffffffffu, s2, off);
        }
        float mean = s * (1.f / 192.f);
        float var  = s2 * (1.f / 192.f) - mean * mean;
        float inv  = rsqrtf(var + 1e-5f);
        size_t r = (size_t)row0 + lr;
        #pragma unroll
        for (int jj = 0; jj < 6; jj++) {
            int k = lane + 32 * jj;
            h2[r * 192 + k] = __float2half_rn((v[jj] - mean) * inv * g2[k] + b2[k]);
        }
    }
}

// ============================================================
// Windowed attention, FA-style register softmax.
// 1 block per (window, head), 128 threads = 4 warps x 16 rows.
// QK^T -> bias (h(n)-h(m)+84 LUT) + softmax entirely in
// registers -> P packed straight into mma A-fragments -> P@V.
// One __syncthreads total; no S/P smem round trips.
// ============================================================
__global__ __launch_bounds__(128) void k_attn(const float* __restrict__ bias_table)
{
    __shared__ __half q_sm[64][40];
    __shared__ __half k_sm[64][40];
    __shared__ __half v_t [32][72];   // V transposed: [dim][token], K=64 padded
    __shared__ float  bt[169];
    __shared__ int    h_sm[64];       // h(t) = 13*(t/7) + t%7

    const int w    = blockIdx.x;
    const int head = blockIdx.y;
    const int tid  = threadIdx.x;
    const int lane = tid & 31;
    const int wid  = tid >> 5;
    const int b    = w >> 6;
    const int wy   = (w >> 3) & 7;
    const int wx   = w & 7;

    for (int i = tid; i < 169; i += 128) bt[i] = bias_table[i * 6 + head];
    if (tid < 64) h_sm[tid] = (tid < 49) ? (13 * (tid / 7) + tid % 7) : 0;

    // load q/k/v (half2 granularity), v transposed
    for (int idx = tid; idx < 784; idx += 128) {
        int n = idx >> 4, dp = idx & 15;
        int ty = n / 7, tx = n - 7 * ty;
        size_t row = ((size_t)(b * 56 + wy * 7 + ty) * 56 + wx * 7 + tx);
        const __half2* base = (const __half2*)(g_qkv + row * 576 + head * 32) + dp;
        __half2 qv = base[0];
        __half2 kv = base[96];
        __half2 vv = base[192];
        *(__half2*)&q_sm[n][2 * dp] = qv;
        *(__half2*)&k_sm[n][2 * dp] = kv;
        v_t[2 * dp][n]     = __low2half(vv);
        v_t[2 * dp + 1][n] = __high2half(vv);
    }
    // zero q/k pad rows 49..63 (defensive) and v_t pad tokens 49..63
    for (int idx = tid; idx < 480; idx += 128) {
        int rr = 49 + (idx >> 5), d = idx & 31;
        q_sm[rr][d] = __float2half(0.f);
        k_sm[rr][d] = __float2half(0.f);
    }
    for (int idx = tid; idx < 32 * 15; idx += 128)
        v_t[idx / 15][49 + idx % 15] = __float2half(0.f);
    __syncthreads();

    const int m0  = wid * 16;
    const int l15 = lane & 15, lhi = lane >> 4;
    const int bnn = ((lane >> 4) & 1) * 8 + (lane & 7);
    const int bkk = ((lane >> 3) & 1) * 8;
    const uint32_t qb = (uint32_t)__cvta_generic_to_shared(q_sm);
    const uint32_t kb = (uint32_t)__cvta_generic_to_shared(k_sm);
    const uint32_t vb = (uint32_t)__cvta_generic_to_shared(v_t);

    // ---- QK^T: warp rows m0..m0+15, cols 0..63, K=32 ----
    float c[8][4];
    #pragma unroll
    for (int j = 0; j < 8; j++)
        #pragma unroll
        for (int q = 0; q < 4; q++) c[j][q] = 0.f;

    #pragma unroll
    for (int ks = 0; ks < 2; ks++) {
        const int k0 = ks * 16;
        uint32_t a[4];
        ldsm_x4(a, qb + (uint32_t)(((m0 + l15) * 40 + k0) * 2 + lhi * 16));
        uint32_t bf[4][4];
        #pragma unroll
        for (int jj = 0; jj < 4; jj++) {
            int nn = jj * 16 + bnn;
            ldsm_x4(bf[jj], kb + (uint32_t)((nn * 40 + k0 + bkk) * 2));
        }
        #pragma unroll
        for (int j = 0; j < 8; j++)
            mma_f16(c[j], a, bf[j >> 1][(j & 1) * 2], bf[j >> 1][(j & 1) * 2 + 1]);
    }

    // ---- bias + softmax in registers (warp owns complete rows) ----
    const int nr0 = m0 + (lane >> 2);      // row for c[j][0..1]
    const int nr1 = nr0 + 8;               // row for c[j][2..3]
    const int hn0 = h_sm[nr0];
    const int hn1 = h_sm[nr1];
    const int mb  = 2 * (lane & 3);

    float mx0 = -1e30f, mx1 = -1e30f;
    #pragma unroll
    for (int j = 0; j < 8; j++) {
        #pragma unroll
        for (int e = 0; e < 2; e++) {
            int m = 8 * j + mb + e;
            if (m < 49) {
                int hm = h_sm[m];
                c[j][e]     += bt[hn0 - hm + 84];
                c[j][2 + e] += bt[hn1 - hm + 84];
                mx0 = fmaxf(mx0, c[j][e]);
                mx1 = fmaxf(mx1, c[j][2 + e]);
            }
        }
    }
    mx0 = fmaxf(mx0, __shfl_xor_sync(0xffffffffu, mx0, 1));
    mx0 = fmaxf(mx0, __shfl_xor_sync(0xffffffffu, mx0, 2));
    mx1 = fmaxf(mx1, __shfl_xor_sync(0xffffffffu, mx1, 1));
    mx1 = fmaxf(mx1, __shfl_xor_sync(0xffffffffu, mx1, 2));

    float s0 = 0.f, s1 = 0.f;
    #pragma unroll
    for (int j = 0; j < 8; j++) {
        #pragma unroll
        for (int e = 0; e < 2; e++) {
            int m = 8 * j + mb + e;
            float p0 = (m < 49) ? __expf(c[j][e]     - mx0) : 0.f;
            float p1 = (m < 49) ? __expf(c[j][2 + e] - mx1) : 0.f;
            c[j][e]     = p0;
            c[j][2 + e] = p1;
            s0 += p0;
            s1 += p1;
        }
    }
    s0 += __shfl_xor_sync(0xffffffffu, s0, 1);
    s0 += __shfl_xor_sync(0xffffffffu, s0, 2);
    s1 += __shfl_xor_sync(0xffffffffu, s1, 1);
    s1 += __shfl_xor_sync(0xffffffffu, s1, 2);
    const float i0 = 1.f / s0;
    const float i1 = 1.f / s1;

    // pack P into mma A fragments: step ks uses C frags 2ks, 2ks+1
    uint32_t ap[4][4];
    #pragma unroll
    for (int ks = 0; ks < 4; ks++) {
        ap[ks][0] = h2u(__floats2half2_rn(c[2*ks][0]   * i0, c[2*ks][1]   * i0));
        ap[ks][1] = h2u(__floats2half2_rn(c[2*ks][2]   * i1, c[2*ks][3]   * i1));
        ap[ks][2] = h2u(__floats2half2_rn(c[2*ks+1][0] * i0, c[2*ks+1][1] * i0));
        ap[ks][3] = h2u(__floats2half2_rn(c[2*ks+1][2] * i1, c[2*ks+1][3] * i1));
    }

    // ---- P @ V: warp rows m0..m0+15, cols 0..31, K=64 ----
    float o[4][4];
    #pragma unroll
    for (int j = 0; j < 4; j++)
        #pragma unroll
        for (int q = 0; q < 4; q++) o[j][q] = 0.f;

    #pragma unroll
    for (int ks = 0; ks < 4; ks++) {
        const int k0 = ks * 16;
        uint32_t bf[2][4];
        #pragma unroll
        for (int jj = 0; jj < 2; jj++) {
            int nn = jj * 16 + bnn;
            ldsm_x4(bf[jj], vb + (uint32_t)((nn * 72 + k0 + bkk) * 2));
        }
        #pragma unroll
        for (int j = 0; j < 4; j++)
            mma_f16(o[j], ap[ks], bf[j >> 1][(j & 1) * 2], bf[j >> 1][(j & 1) * 2 + 1]);
    }

    // scatter to unshifted layout (fp16)
    {
        #pragma unroll
        for (int h = 0; h < 2; h++) {
            const int n = nr0 + 8 * h;
            if (n < 49) {
                int ty = n / 7, tx = n - 7 * ty;
                int oi = wy * 7 + ty + 3; if (oi >= 56) oi -= 56;
                int oj = wx * 7 + tx + 3; if (oj >= 56) oj -= 56;
                __half* dst = g_ao + ((size_t)(b * 56 + oi) * 56 + oj) * 192 + head * 32;
                #pragma unroll
                for (int j = 0; j < 4; j++) {
                    int d = 8 * j + 2 * (lane & 3);
                    *(__half2*)&dst[d] = __floats2half2_rn(o[j][2 * h + 0], o[j][2 * h + 1]);
                }
            }
        }
    }
}

// ============================================================
extern "C" void kernel_launch(void* const* d_in, const int* in_sizes, int n_in,
                              void* d_out, int out_size)
{
    (void)in_sizes; (void)n_in; (void)out_size;
    const float* x          = (const float*)d_in[0];
    const float* qkv_w      = (const float*)d_in[1];
    const float* qkv_b      = (const float*)d_in[2];
    const float* proj_w     = (const float*)d_in[3];
    const float* proj_b     = (const float*)d_in[4];
    const float* bias_table = (const float*)d_in[5];
    const float* n1g        = (const float*)d_in[6];
    const float* n1b        = (const float*)d_in[7];
    const float* n2g        = (const float*)d_in[8];
    const float* n2b        = (const float*)d_in[9];
    const float* w1         = (const float*)d_in[10];
    const float* b1         = (const float*)d_in[11];
    const float* w2         = (const float*)d_in[12];
    const float* b2         = (const float*)d_in[13];
    float* out = (float*)d_out;

    __half* p_ln   = nullptr; cudaGetSymbolAddress((void**)&p_ln,   g_ln);
    __half* p_qkv  = nullptr; cudaGetSymbolAddress((void**)&p_qkv,  g_qkv);
    __half* p_ao   = nullptr; cudaGetSymbolAddress((void**)&p_ao,   g_ao);
    float*  p_x2   = nullptr; cudaGetSymbolAddress((void**)&p_x2,   g_x2);
    __half* p_h2   = nullptr; cudaGetSymbolAddress((void**)&p_h2,   g_h2);
    __half* p_hid  = nullptr; cudaGetSymbolAddress((void**)&p_hid,  g_hid);
    __half* p_qkvT = nullptr; cudaGetSymbolAddress((void**)&p_qkvT, g_qkvT);
    __half* p_projT= nullptr; cudaGetSymbolAddress((void**)&p_projT,g_projT);
    __half* p_w1T  = nullptr; cudaGetSymbolAddress((void**)&p_w1T,  g_w1T);
    __half* p_w2T  = nullptr; cudaGetSymbolAddress((void**)&p_w2T,  g_w2T);

    cudaFuncSetAttribute(k_gemm<0,192,576,__half>, cudaFuncAttributeMaxDynamicSharedMemorySize, GEMM_SMEM);
    cudaFuncSetAttribute(k_gemm<1,192,768,__half>, cudaFuncAttributeMaxDynamicSharedMemorySize, GEMM_SMEM);
    cudaFuncSetAttribute(k_gemm<2,768,192,float>,  cudaFuncAttributeMaxDynamicSharedMemorySize, GEMM_SMEM);
    cudaFuncSetAttribute(k_proj_ln, cudaFuncAttributeMaxDynamicSharedMemorySize, PROJ_SMEM);

    // all weight transposes in one launch (fp16)
    k_transpose_all<<<432, 256>>>(qkv_w, proj_w, w1, w2,
                                  p_qkvT, p_projT, p_w1T, p_w2T);

    // LN1 + shift
    k_ln1<<<6272, 256>>>(x, n1g, n1b, p_ln);
    // QKV GEMM (q pre-scaled, fp16 out)
    k_gemm<0,192,576,__half><<<dim3(392, 6), 128, GEMM_SMEM>>>(p_ln, p_qkvT, qkv_b, nullptr, p_qkv);
    // attention (register-softmax fp16 tensor-core)
    k_attn<<<dim3(1024, 6), 128>>>(bias_table);
    // proj GEMM + residual + fused LN2
    k_proj_ln<<<392, 256, PROJ_SMEM>>>(p_ao, p_projT, proj_b, x, n2g, n2b, p_x2, p_h2);
    // MLP
    k_gemm<1,192,768,__half><<<dim3(392, 8), 128, GEMM_SMEM>>>(p_h2, p_w1T, b1, nullptr, p_hid);
    k_gemm<2,768,192,float><<<dim3(392, 2), 128, GEMM_SMEM>>>(p_hid, p_w2T, b2, p_x2, out);
}

// round 17
// speedup vs baseline: 5.5226x; 1.0430x over previous
#include <cuda_runtime.h>
#include <cuda_fp16.h>
#include <math.h>
#include <stdint.h>

// ---------------- problem constants ----------------
#define TTOK 50176            // 16*56*56 tokens
#define CC   192
#define HID  768

// ---------------- scratch ----------------
__device__ __half g_ln [(size_t)TTOK * CC];    // LN1(x), SHIFTED layout, fp16
__device__ __half g_qkv[(size_t)TTOK * 576];   // qkv, shifted layout, q pre-scaled, fp16
__device__ __half g_ao [(size_t)TTOK * CC];    // attn out, UNSHIFTED, fp16
__device__ float  g_x2 [(size_t)TTOK * CC];    // residual stream after attn (fp32)
__device__ __half g_h2 [(size_t)TTOK * CC];    // LN2 out, fp16
__device__ __half g_hid[(size_t)TTOK * HID];   // MLP hidden, fp16
// transposed fp16 weights: WT[n][k]
__device__ __half g_qkvT[576 * 192];
__device__ __half g_projT[192 * 192];
__device__ __half g_w1T [768 * 192];
__device__ __half g_w2T [192 * 768];

// ---------------- helpers ----------------
__device__ __forceinline__ uint32_t h2u(__half2 h) {
    uint32_t u; *(__half2*)&u = h; return u;
}
__device__ __forceinline__ void ldsm_x4(uint32_t* r, uint32_t addr) {
    asm volatile("ldmatrix.sync.aligned.m8n8.x4.shared.b16 {%0,%1,%2,%3}, [%4];"
        : "=r"(r[0]), "=r"(r[1]), "=r"(r[2]), "=r"(r[3]) : "r"(addr));
}
__device__ __forceinline__ void ldsm_x4_t(uint32_t* r, uint32_t addr) {
    asm volatile("ldmatrix.sync.aligned.m8n8.x4.trans.shared.b16 {%0,%1,%2,%3}, [%4];"
        : "=r"(r[0]), "=r"(r[1]), "=r"(r[2]), "=r"(r[3]) : "r"(addr));
}
__device__ __forceinline__ void mma_f16(float* c, const uint32_t* a,
                                        uint32_t b0, uint32_t b1) {
    asm volatile(
        "mma.sync.aligned.m16n8k16.row.col.f32.f16.f16.f32 "
        "{%0,%1,%2,%3}, {%4,%5,%6,%7}, {%8,%9}, {%0,%1,%2,%3};"
        : "+f"(c[0]), "+f"(c[1]), "+f"(c[2]), "+f"(c[3])
        : "r"(a[0]), "r"(a[1]), "r"(a[2]), "r"(a[3]), "r"(b0), "r"(b1));
}
__device__ __forceinline__ void cpa16(uint32_t dst, const void* src) {
    asm volatile("cp.async.cg.shared.global [%0], [%1], 16;" :: "r"(dst), "l"(src));
}

// ============================================================
// LayerNorm1 + cyclic shift. Output fp16.
// ============================================================
__global__ __launch_bounds__(256) void k_ln1(
    const float* __restrict__ in, const float* __restrict__ g,
    const float* __restrict__ b, __half* __restrict__ o)
{
    const int p    = blockIdx.x * 8 + (threadIdx.x >> 5);
    const int lane = threadIdx.x & 31;
    int bb = p / 3136, rem = p % 3136;
    int i = rem / 56, j = rem % 56;
    int si = i + 3; if (si >= 56) si -= 56;
    int sj = j + 3; if (sj >= 56) sj -= 56;
    const float* src = in + ((size_t)(bb * 56 + si) * 56 + sj) * 192;
    float v[6]; float s = 0.f, s2 = 0.f;
    #pragma unroll
    for (int jj = 0; jj < 6; jj++) {
        v[jj] = src[lane + 32 * jj];
        s  += v[jj];
        s2 += v[jj] * v[jj];
    }
    #pragma unroll
    for (int off = 16; off > 0; off >>= 1) {
        s  += __shfl_xor_sync(0xffffffffu, s,  off);
        s2 += __shfl_xor_sync(0xffffffffu, s2, off);
    }
    float mean = s * (1.f / 192.f);
    float var  = s2 * (1.f / 192.f) - mean * mean;
    float inv  = rsqrtf(var + 1e-5f);
    __half* dst = o + (size_t)p * 192;
    #pragma unroll
    for (int jj = 0; jj < 6; jj++) {
        int k = lane + 32 * jj;
        dst[k] = __float2half_rn((v[jj] - mean) * inv * g[k] + b[k]);
    }
}

// ============================================================
// All 4 weight transposes in ONE launch. [K][N] -> [N][K], fp16.
// ============================================================
__global__ __launch_bounds__(256) void k_transpose_all(
    const float* __restrict__ qkv_w, const float* __restrict__ proj_w,
    const float* __restrict__ w1,    const float* __restrict__ w2,
    __half* __restrict__ qkvT, __half* __restrict__ projT,
    __half* __restrict__ w1T,  __half* __restrict__ w2T)
{
    __shared__ float t[32][33];
    const int bid = blockIdx.x;
    const float* W; __half* WT; int K, N, bi;
    if (bid < 108)      { W = qkv_w;  WT = qkvT;  K = 192; N = 576; bi = bid; }
    else if (bid < 144) { W = proj_w; WT = projT; K = 192; N = 192; bi = bid - 108; }
    else if (bid < 288) { W = w1;     WT = w1T;   K = 192; N = 768; bi = bid - 144; }
    else                { W = w2;     WT = w2T;   K = 768; N = 192; bi = bid - 288; }
    const int nb = N / 32;
    const int bn = (bi % nb) * 32, bk = (bi / nb) * 32;
    const int tx = threadIdx.x & 31, ty = threadIdx.x >> 5;
    #pragma unroll
    for (int i = 0; i < 4; i++)
        t[ty + 8 * i][tx] = W[(size_t)(bk + ty + 8 * i) * N + bn + tx];
    __syncthreads();
    #pragma unroll
    for (int i = 0; i < 4; i++)
        WT[(size_t)(bn + ty + 8 * i) * K + bk + tx] = __float2half_rn(t[tx][ty + 8 * i]);
}

// ============================================================
// FP16 mma.sync GEMM: out[M,ND] = A[M,KD] @ WT[ND,KD]^T + epi
// block tile 128x96, BK=64 halfs, 4 warps (2M x 2N), warp tile
// 64x48. Double-buffered cp.async; 2 syncs per 64-wide slab.
// ============================================================
#define AS2 72                          // halfs per smem row (144 B)
#define ASLAB2 (128 * AS2)
#define BSLAB2 (96 * AS2)
#define GEMM_SMEM ((2 * ASLAB2 + 2 * BSLAB2) * 2)   // 64512 B

template<int EPI, int KD, int ND, typename OutT>
__global__ __launch_bounds__(128, 3) void k_gemm(
    const __half* __restrict__ A, const __half* __restrict__ WT,
    const float* __restrict__ bias, const float* __restrict__ res,
    OutT* __restrict__ out)
{
    extern __shared__ __half hsm[];
    __half* a_buf[2] = { hsm,              hsm + ASLAB2 };
    __half* b_buf[2] = { hsm + 2 * ASLAB2, hsm + 2 * ASLAB2 + BSLAB2 };

    const int tid   = threadIdx.x;
    const int lane  = tid & 31;
    const int wid   = tid >> 5;
    const int m0    = (wid >> 1) * 64;
    const int n0    = (wid & 1) * 48;
    const int row0  = blockIdx.x * 128;
    const int col0  = blockIdx.y * 96;

    float c[4][6][4];
    #pragma unroll
    for (int i = 0; i < 4; i++)
        #pragma unroll
        for (int j = 0; j < 6; j++)
            #pragma unroll
            for (int q = 0; q < 4; q++) c[i][j][q] = 0.f;

    auto load_slab = [&](int kc, int bi) {
        uint32_t ab = (uint32_t)__cvta_generic_to_shared(a_buf[bi]);
        uint32_t bb = (uint32_t)__cvta_generic_to_shared(b_buf[bi]);
        #pragma unroll
        for (int i = 0; i < 8; i++) {              // A: 128 rows x 8 chunks(8h)
            int idx = tid + 128 * i;
            int r = idx >> 3, ch = idx & 7;
            cpa16(ab + (uint32_t)(r * AS2 + ch * 8) * 2,
                  A + (size_t)(row0 + r) * KD + kc + ch * 8);
        }
        #pragma unroll
        for (int i = 0; i < 6; i++) {              // B: 96 rows x 8 chunks
            int idx = tid + 128 * i;
            int r = idx >> 3, ch = idx & 7;
            cpa16(bb + (uint32_t)(r * AS2 + ch * 8) * 2,
                  WT + (size_t)(col0 + r) * KD + kc + ch * 8);
        }
    };

    constexpr int S = KD / 64;
    load_slab(0, 0);
    asm volatile("cp.async.commit_group;");

    const int l15 = lane & 15;
    const int lhi = lane >> 4;
    const int bnn = ((lane >> 4) & 1) * 8 + (lane & 7);
    const int bkk = ((lane >> 3) & 1) * 8;

    for (int s = 0; s < S; s++) {
        const int buf = s & 1;
        if (s + 1 < S) {
            load_slab((s + 1) * 64, buf ^ 1);
            asm volatile("cp.async.commit_group;");
            asm volatile("cp.async.wait_group 1;");
        } else {
            asm volatile("cp.async.wait_group 0;");
        }
        __syncthreads();

        const uint32_t a_base = (uint32_t)__cvta_generic_to_shared(a_buf[buf]);
        const uint32_t b_base = (uint32_t)__cvta_generic_to_shared(b_buf[buf]);

        #pragma unroll
        for (int ks = 0; ks < 4; ks++) {
            const int k0 = ks * 16;
            uint32_t a[4][4];
            #pragma unroll
            for (int i = 0; i < 4; i++) {
                uint32_t addr = a_base
                    + (uint32_t)(((m0 + 16 * i + l15) * AS2 + k0) * 2 + lhi * 16);
                ldsm_x4(a[i], addr);
            }
            uint32_t bf[3][4];
            #pragma unroll
            for (int jj = 0; jj < 3; jj++) {
                int nn = n0 + jj * 16 + bnn;
                uint32_t addr = b_base + (uint32_t)((nn * AS2 + k0 + bkk) * 2);
                ldsm_x4(bf[jj], addr);
            }
            #pragma unroll
            for (int i = 0; i < 4; i++)
                #pragma unroll
                for (int j = 0; j < 6; j++)
                    mma_f16(c[i][j], a[i], bf[j >> 1][(j & 1) * 2],
                                            bf[j >> 1][(j & 1) * 2 + 1]);
        }
        __syncthreads();
    }

    const float qscale = 0.17677669529663687f;
    #pragma unroll
    for (int i = 0; i < 4; i++) {
        #pragma unroll
        for (int j = 0; j < 6; j++) {
            int gc = col0 + n0 + 8 * j + (lane & 3) * 2;
            float2 bb = *(const float2*)&bias[gc];
            #pragma unroll
            for (int h = 0; h < 2; h++) {
                size_t r = (size_t)row0 + m0 + 16 * i + (lane >> 2) + 8 * h;
                float v0 = c[i][j][2 * h + 0] + bb.x;
                float v1 = c[i][j][2 * h + 1] + bb.y;
                if (EPI == 0) {
                    if (gc < 192) { v0 *= qscale; v1 *= qscale; }
                    *(__half2*)&out[r * ND + gc] = __floats2half2_rn(v0, v1);
                } else if (EPI == 1) {
                    v0 = 0.5f * v0 * (1.0f + erff(v0 * 0.70710678118654752f));
                    v1 = 0.5f * v1 * (1.0f + erff(v1 * 0.70710678118654752f));
                    *(__half2*)&out[r * ND + gc] = __floats2half2_rn(v0, v1);
                } else {
                    float2 rr = *(const float2*)&res[r * ND + gc];
                    v0 += rr.x; v1 += rr.y;
                    *(float2*)&out[r * ND + gc] = make_float2(v0, v1);
                }
            }
        }
    }
}

// ============================================================
// Proj GEMM (128x192 full-width tile) + residual + fused LN2.
// (BK=32 path, unchanged from R16)
// ============================================================
#define AS 40
#define ASLAB_P (128 * AS)
#define BSLAB_P (192 * AS)
#define PROJ_SMEM (128 * 196 * 4)

__global__ __launch_bounds__(256) void k_proj_ln(
    const __half* __restrict__ A, const __half* __restrict__ WT,
    const float* __restrict__ bias, const float* __restrict__ x,
    const float* __restrict__ g2, const float* __restrict__ b2,
    float* __restrict__ x2, __half* __restrict__ h2)
{
    extern __shared__ float sm[];
    __half* hsm = (__half*)sm;
    __half* a_buf[2] = { hsm,               hsm + ASLAB_P };
    __half* b_buf[2] = { hsm + 2 * ASLAB_P, hsm + 2 * ASLAB_P + BSLAB_P };
    float* stage = sm;

    const int tid  = threadIdx.x;
    const int lane = tid & 31;
    const int wid  = tid >> 5;
    const int m0   = (wid >> 2) * 64;
    const int n0   = (wid & 3) * 48;
    const int row0 = blockIdx.x * 128;

    float c[4][6][4];
    #pragma unroll
    for (int i = 0; i < 4; i++)
        #pragma unroll
        for (int j = 0; j < 6; j++)
            #pragma unroll
            for (int q = 0; q < 4; q++) c[i][j][q] = 0.f;

    auto load_slab = [&](int kc, int bi) {
        uint32_t ab = (uint32_t)__cvta_generic_to_shared(a_buf[bi]);
        uint32_t bb = (uint32_t)__cvta_generic_to_shared(b_buf[bi]);
        #pragma unroll
        for (int i = 0; i < 2; i++) {
            int idx = tid + 256 * i;
            int r = idx >> 2, ch = idx & 3;
            cpa16(ab + (uint32_t)(r * AS + ch * 8) * 2,
                  A + (size_t)(row0 + r) * 192 + kc + ch * 8);
        }
        #pragma unroll
        for (int i = 0; i < 3; i++) {
            int idx = tid + 256 * i;
            int r = idx >> 2, ch = idx & 3;
            cpa16(bb + (uint32_t)(r * AS + ch * 8) * 2,
                  WT + (size_t)r * 192 + kc + ch * 8);
        }
    };

    load_slab(0, 0);
    asm volatile("cp.async.commit_group;");

    const int l15 = lane & 15;
    const int lhi = lane >> 4;
    const int bnn = ((lane >> 4) & 1) * 8 + (lane & 7);
    const int bkk = ((lane >> 3) & 1) * 8;

    for (int s = 0; s < 6; s++) {
        const int buf = s & 1;
        if (s + 1 < 6) {
            load_slab((s + 1) * 32, buf ^ 1);
            asm volatile("cp.async.commit_group;");
            asm volatile("cp.async.wait_group 1;");
        } else {
            asm volatile("cp.async.wait_group 0;");
        }
        __syncthreads();

        const uint32_t a_base = (uint32_t)__cvta_generic_to_shared(a_buf[buf]);
        const uint32_t b_base = (uint32_t)__cvta_generic_to_shared(b_buf[buf]);

        #pragma unroll
        for (int ks = 0; ks < 2; ks++) {
            const int k0 = ks * 16;
            uint32_t a[4][4];
            #pragma unroll
            for (int i = 0; i < 4; i++) {
                uint32_t addr = a_base
                    + (uint32_t)(((m0 + 16 * i + l15) * AS + k0) * 2 + lhi * 16);
                ldsm_x4(a[i], addr);
            }
            uint32_t bf[3][4];
            #pragma unroll
            for (int jj = 0; jj < 3; jj++) {
                int nn = n0 + jj * 16 + bnn;
                uint32_t addr = b_base + (uint32_t)((nn * AS + k0 + bkk) * 2);
                ldsm_x4(bf[jj], addr);
            }
            #pragma unroll
            for (int i = 0; i < 4; i++)
                #pragma unroll
                for (int j = 0; j < 6; j++)
                    mma_f16(c[i][j], a[i], bf[j >> 1][(j & 1) * 2],
                                            bf[j >> 1][(j & 1) * 2 + 1]);
        }
        __syncthreads();
    }

    #pragma unroll
    for (int i = 0; i < 4; i++) {
        #pragma unroll
        for (int j = 0; j < 6; j++) {
            int gc = n0 + 8 * j + (lane & 3) * 2;
            float2 bb = *(const float2*)&bias[gc];
            #pragma unroll
            for (int h = 0; h < 2; h++) {
                int lr = m0 + 16 * i + (lane >> 2) + 8 * h;
                size_t r = (size_t)row0 + lr;
                float2 rr = *(const float2*)&x[r * 192 + gc];
                float v0 = c[i][j][2 * h + 0] + bb.x + rr.x;
                float v1 = c[i][j][2 * h + 1] + bb.y + rr.y;
                *(float2*)&x2[r * 192 + gc] = make_float2(v0, v1);
                *(float2*)&stage[lr * 196 + gc] = make_float2(v0, v1);
            }
        }
    }
    __syncthreads();

    #pragma unroll 1
    for (int it = 0; it < 16; it++) {
        int lr = wid * 16 + it;
        float v[6]; float s = 0.f, s2 = 0.f;
        #pragma unroll
        for (int jj = 0; jj < 6; jj++) {
            v[jj] = stage[lr * 196 + lane + 32 * jj];
            s  += v[jj];
            s2 += v[jj] * v[jj];
        }
        #pragma unroll
        for (int off = 16; off > 0; off >>= 1) {
            s  += __shfl_xor_sync(0xffffffffu, s,  off);
            s2 += __shfl_xor_sync(0xffffffffu, s2, off);
        }
        float mean = s * (1.f / 192.f);
        float var  = s2 * (1.f / 192.f) - mean * mean;
        float inv  = rsqrtf(var + 1e-5f);
        size_t r = (size_t)row0 + lr;
        #pragma unroll
        for (int jj = 0; jj < 6; jj++) {
            int k = lane + 32 * jj;
            h2[r * 192 + k] = __float2half_rn((v[jj] - mean) * inv * g2[k] + b2[k]);
        }
    }
}

// ============================================================
// Windowed attention, FA-style register softmax.
// float4 vectorized loads; V consumed via ldmatrix.trans from
// natural [token][dim] layout (no transposed staging buffer).
// ============================================================
__global__ __launch_bounds__(128) void k_attn(const float* __restrict__ bias_table)
{
    __shared__ __half q_sm[64][40];
    __shared__ __half k_sm[64][40];
    __shared__ __half v_sm[64][40];   // [token][dim], pad rows zeroed
    __shared__ float  bt[169];
    __shared__ int    h_sm[64];       // h(t) = 13*(t/7) + t%7

    const int w    = blockIdx.x;
    const int head = blockIdx.y;
    const int tid  = threadIdx.x;
    const int lane = tid & 31;
    const int wid  = tid >> 5;
    const int b    = w >> 6;
    const int wy   = (w >> 3) & 7;
    const int wx   = w & 7;

    for (int i = tid; i < 169; i += 128) bt[i] = bias_table[i * 6 + head];
    if (tid < 64) h_sm[tid] = (tid < 49) ? (13 * (tid / 7) + tid % 7) : 0;

    // load q/k/v as float4 (8 halfs per chunk, 4 chunks per 32-dim row)
    for (int idx = tid; idx < 196; idx += 128) {
        int n = idx >> 2, ch = idx & 3;
        int ty = n / 7, tx = n - 7 * ty;
        size_t row = ((size_t)(b * 56 + wy * 7 + ty) * 56 + wx * 7 + tx);
        const float4* base = (const float4*)(g_qkv + row * 576 + head * 32);
        *(float4*)&q_sm[n][ch * 8] = base[ch];        // q
        *(float4*)&k_sm[n][ch * 8] = base[24 + ch];   // +192 halfs
        *(float4*)&v_sm[n][ch * 8] = base[48 + ch];   // +384 halfs
    }
    // zero pad rows 49..63 (cols 0..31) of q/k/v
    for (int idx = tid; idx < 480; idx += 128) {
        int rr = 49 + (idx >> 5), d = idx & 31;
        q_sm[rr][d] = __float2half(0.f);
        k_sm[rr][d] = __float2half(0.f);
        v_sm[rr][d] = __float2half(0.f);
    }
    __syncthreads();

    const int m0  = wid * 16;
    const int l15 = lane & 15, lhi = lane >> 4;
    const int bnn = ((lane >> 4) & 1) * 8 + (lane & 7);
    const int bkk = ((lane >> 3) & 1) * 8;
    const uint32_t qb = (uint32_t)__cvta_generic_to_shared(q_sm);
    const uint32_t kb = (uint32_t)__cvta_generic_to_shared(k_sm);
    const uint32_t vb = (uint32_t)__cvta_generic_to_shared(v_sm);

    // ---- QK^T: warp rows m0..m0+15, cols 0..63, K=32 ----
    float c[8][4];
    #pragma unroll
    for (int j = 0; j < 8; j++)
        #pragma unroll
        for (int q = 0; q < 4; q++) c[j][q] = 0.f;

    #pragma unroll
    for (int ks = 0; ks < 2; ks++) {
        const int k0 = ks * 16;
        uint32_t a[4];
        ldsm_x4(a, qb + (uint32_t)(((m0 + l15) * 40 + k0) * 2 + lhi * 16));
        uint32_t bf[4][4];
        #pragma unroll
        for (int jj = 0; jj < 4; jj++) {
            int nn = jj * 16 + bnn;
            ldsm_x4(bf[jj], kb + (uint32_t)((nn * 40 + k0 + bkk) * 2));
        }
        #pragma unroll
        for (int j = 0; j < 8; j++)
            mma_f16(c[j], a, bf[j >> 1][(j & 1) * 2], bf[j >> 1][(j & 1) * 2 + 1]);
    }

    // ---- bias + softmax in registers ----
    const int nr0 = m0 + (lane >> 2);
    const int nr1 = nr0 + 8;
    const int hn0 = h_sm[nr0];
    const int hn1 = h_sm[nr1];
    const int mb  = 2 * (lane & 3);

    float mx0 = -1e30f, mx1 = -1e30f;
    #pragma unroll
    for (int j = 0; j < 8; j++) {
        #pragma unroll
        for (int e = 0; e < 2; e++) {
            int m = 8 * j + mb + e;
            if (m < 49) {
                int hm = h_sm[m];
                c[j][e]     += bt[hn0 - hm + 84];
                c[j][2 + e] += bt[hn1 - hm + 84];
                mx0 = fmaxf(mx0, c[j][e]);
                mx1 = fmaxf(mx1, c[j][2 + e]);
            }
        }
    }
    mx0 = fmaxf(mx0, __shfl_xor_sync(0xffffffffu, mx0, 1));
    mx0 = fmaxf(mx0, __shfl_xor_sync(0xffffffffu, mx0, 2));
    mx1 = fmaxf(mx1, __shfl_xor_sync(0xffffffffu, mx1, 1));
    mx1 = fmaxf(mx1, __shfl_xor_sync(0xffffffffu, mx1, 2));

    float s0 = 0.f, s1 = 0.f;
    #pragma unroll
    for (int j = 0; j < 8; j++) {
        #pragma unroll
        for (int e = 0; e < 2; e++) {
            int m = 8 * j + mb + e;
            float p0 = (m < 49) ? __expf(c[j][e]     - mx0) : 0.f;
            float p1 = (m < 49) ? __expf(c[j][2 + e] - mx1) : 0.f;
            c[j][e]     = p0;
            c[j][2 + e] = p1;
            s0 += p0;
            s1 += p1;
        }
    }
    s0 += __shfl_xor_sync(0xffffffffu, s0, 1);
    s0 += __shfl_xor_sync(0xffffffffu, s0, 2);
    s1 += __shfl_xor_sync(0xffffffffu, s1, 1);
    s1 += __shfl_xor_sync(0xffffffffu, s1, 2);
    const float i0 = 1.f / s0;
    const float i1 = 1.f / s1;

    // pack P into mma A fragments
    uint32_t ap[4][4];
    #pragma unroll
    for (int ks = 0; ks < 4; ks++) {
        ap[ks][0] = h2u(__floats2half2_rn(c[2*ks][0]   * i0, c[2*ks][1]   * i0));
        ap[ks][1] = h2u(__floats2half2_rn(c[2*ks][2]   * i1, c[2*ks][3]   * i1));
        ap[ks][2] = h2u(__floats2half2_rn(c[2*ks+1][0] * i0, c[2*ks+1][1] * i0));
        ap[ks][3] = h2u(__floats2half2_rn(c[2*ks+1][2] * i1, c[2*ks+1][3] * i1));
    }

    // ---- P @ V: K=64 (tokens), B-fragments via trans-ldsm ----
    float o[4][4];
    #pragma unroll
    for (int j = 0; j < 4; j++)
        #pragma unroll
        for (int q = 0; q < 4; q++) o[j][q] = 0.f;

    const int vtok = ((lane >> 3) & 1) * 8 + (lane & 7);  // token offset in k-block
    const int vdim = (lane >> 4) * 8;                     // dim offset in n-block
    #pragma unroll
    for (int ks = 0; ks < 4; ks++) {
        const int k0 = ks * 16;
        uint32_t bf[2][4];
        #pragma unroll
        for (int jj = 0; jj < 2; jj++) {
            uint32_t addr = vb + (uint32_t)(((k0 + vtok) * 40 + jj * 16 + vdim) * 2);
            ldsm_x4_t(bf[jj], addr);
        }
        #pragma unroll
        for (int j = 0; j < 4; j++)
            mma_f16(o[j], ap[ks], bf[j >> 1][(j & 1) * 2], bf[j >> 1][(j & 1) * 2 + 1]);
    }

    // scatter to unshifted layout (fp16)
    {
        #pragma unroll
        for (int h = 0; h < 2; h++) {
            const int n = nr0 + 8 * h;
            if (n < 49) {
                int ty = n / 7, tx = n - 7 * ty;
                int oi = wy * 7 + ty + 3; if (oi >= 56) oi -= 56;
                int oj = wx * 7 + tx + 3; if (oj >= 56) oj -= 56;
                __half* dst = g_ao + ((size_t)(b * 56 + oi) * 56 + oj) * 192 + head * 32;
                #pragma unroll
                for (int j = 0; j < 4; j++) {
                    int d = 8 * j + 2 * (lane & 3);
                    *(__half2*)&dst[d] = __floats2half2_rn(o[j][2 * h + 0], o[j][2 * h + 1]);
                }
            }
        }
    }
}

// ============================================================
extern "C" void kernel_launch(void* const* d_in, const int* in_sizes, int n_in,
                              void* d_out, int out_size)
{
    (void)in_sizes; (void)n_in; (void)out_size;
    const float* x          = (const float*)d_in[0];
    const float* qkv_w      = (const float*)d_in[1];
    const float* qkv_b      = (const float*)d_in[2];
    const float* proj_w     = (const float*)d_in[3];
    const float* proj_b     = (const float*)d_in[4];
    const float* bias_table = (const float*)d_in[5];
    const float* n1g        = (const float*)d_in[6];
    const float* n1b        = (const float*)d_in[7];
    const float* n2g        = (const float*)d_in[8];
    const float* n2b        = (const float*)d_in[9];
    const float* w1         = (const float*)d_in[10];
    const float* b1         = (const float*)d_in[11];
    const float* w2         = (const float*)d_in[12];
    const float* b2         = (const float*)d_in[13];
    float* out = (float*)d_out;

    __half* p_ln   = nullptr; cudaGetSymbolAddress((void**)&p_ln,   g_ln);
    __half* p_qkv  = nullptr; cudaGetSymbolAddress((void**)&p_qkv,  g_qkv);
    __half* p_ao   = nullptr; cudaGetSymbolAddress((void**)&p_ao,   g_ao);
    float*  p_x2   = nullptr; cudaGetSymbolAddress((void**)&p_x2,   g_x2);
    __half* p_h2   = nullptr; cudaGetSymbolAddress((void**)&p_h2,   g_h2);
    __half* p_hid  = nullptr; cudaGetSymbolAddress((void**)&p_hid,  g_hid);
    __half* p_qkvT = nullptr; cudaGetSymbolAddress((void**)&p_qkvT, g_qkvT);
    __half* p_projT= nullptr; cudaGetSymbolAddress((void**)&p_projT,g_projT);
    __half* p_w1T  = nullptr; cudaGetSymbolAddress((void**)&p_w1T,  g_w1T);
    __half* p_w2T  = nullptr; cudaGetSymbolAddress((void**)&p_w2T,  g_w2T);

    cudaFuncSetAttribute(k_gemm<0,192,576,__half>, cudaFuncAttributeMaxDynamicSharedMemorySize, GEMM_SMEM);
    cudaFuncSetAttribute(k_gemm<1,192,768,__half>, cudaFuncAttributeMaxDynamicSharedMemorySize, GEMM_SMEM);
    cudaFuncSetAttribute(k_gemm<2,768,192,float>,  cudaFuncAttributeMaxDynamicSharedMemorySize, GEMM_SMEM);
    cudaFuncSetAttribute(k_proj_ln, cudaFuncAttributeMaxDynamicSharedMemorySize, PROJ_SMEM);

    // all weight transposes in one launch (fp16)
    k_transpose_all<<<432, 256>>>(qkv_w, proj_w, w1, w2,
                                  p_qkvT, p_projT, p_w1T, p_w2T);

    // LN1 + shift
    k_ln1<<<6272, 256>>>(x, n1g, n1b, p_ln);
    // QKV GEMM (q pre-scaled, fp16 out)
    k_gemm<0,192,576,__half><<<dim3(392, 6), 128, GEMM_SMEM>>>(p_ln, p_qkvT, qkv_b, nullptr, p_qkv);
    // attention (register-softmax fp16 tensor-core)
    k_attn<<<dim3(1024, 6), 128>>>(bias_table);
    // proj GEMM + residual + fused LN2
    k_proj_ln<<<392, 256, PROJ_SMEM>>>(p_ao, p_projT, proj_b, x, n2g, n2b, p_x2, p_h2);
    // MLP
    k_gemm<1,192,768,__half><<<dim3(392, 8), 128, GEMM_SMEM>>>(p_h2, p_w1T, b1, nullptr, p_hid);
    k_gemm<2,768,192,float><<<dim3(392, 2), 128, GEMM_SMEM>>>(p_hid, p_w2T, b2, p_x2, out);
}